// round 1
// baseline (speedup 1.0000x reference)
#include <cuda_runtime.h>
#include <cuda_bf16.h>
#include <math.h>

// ---------------------------------------------------------------------------
// Problem constants
// ---------------------------------------------------------------------------
#define BATCH 128
#define SEQ   49          // 7*7
#define FDIM  2048        // conv feature dim
#define D     768
#define KQ    100         // num queries
#define NHEAD 8
#define HD    96          // D / NHEAD
#define FF    2048
#define NC    1000
#define GRP   10
#define EPS   1e-5f

// ---------------------------------------------------------------------------
// Scratch (static device globals; no allocation allowed)
// ---------------------------------------------------------------------------
__device__ float g_mem  [BATCH * SEQ * D];   // embedded memory   (B*49, 768)
__device__ float g_kbuf [BATCH * SEQ * D];   // K projection
__device__ float g_vbuf [BATCH * SEQ * D];   // V projection
__device__ float g_tgtln[KQ * D];            // layernorm(2*query_embed)
__device__ float g_q    [KQ * D];            // Q projection (batch independent)
__device__ float g_ctx  [BATCH * KQ * D];    // attention context
__device__ float g_tmp  [BATCH * KQ * D];    // ctx @ wo + bo
__device__ float g_tgt2 [BATCH * KQ * D];    // after 2nd layernorm
__device__ float g_h1   [BATCH * KQ * FF];   // FFN hidden
__device__ float g_h2   [BATCH * KQ * D];    // FFN out
__device__ float g_h    [BATCH * KQ * D];    // after 3rd layernorm

// ---------------------------------------------------------------------------
// Block-wide sum (256 threads)
// ---------------------------------------------------------------------------
__device__ __forceinline__ float block_sum(float v, float* sred) {
    int lane = threadIdx.x & 31, w = threadIdx.x >> 5;
    #pragma unroll
    for (int o = 16; o > 0; o >>= 1) v += __shfl_down_sync(0xffffffffu, v, o);
    if (lane == 0) sred[w] = v;
    __syncthreads();
    float s = (threadIdx.x < 8) ? sred[threadIdx.x] : 0.0f;
    if (w == 0) {
        #pragma unroll
        for (int o = 4; o > 0; o >>= 1) s += __shfl_down_sync(0xffffffffu, s, o);
        if (lane == 0) sred[0] = s;
    }
    __syncthreads();
    float r = sred[0];
    __syncthreads();   // allow caller to reuse sred
    return r;
}

// ---------------------------------------------------------------------------
// Generic SGEMM: C[M,N] = A[M,K] @ B[K,N] + bias (+ optional ReLU)
// 64x64 tile, BK=16, 256 threads, 4x4 per thread. N,K multiples of 16 here.
// ---------------------------------------------------------------------------
#define BM 64
#define BN 64
#define BKt 16

template<bool RELU>
__global__ __launch_bounds__(256)
void sgemm(const float* __restrict__ A, const float* __restrict__ Bm,
           const float* __restrict__ bias, float* __restrict__ C,
           int M, int N, int K)
{
    __shared__ float As[BKt][BM];
    __shared__ float Bs[BKt][BN];
    const int tid = threadIdx.x;
    const int n0 = blockIdx.x * BN;
    const int m0 = blockIdx.y * BM;
    const int tx = tid & 15, ty = tid >> 4;
    const int ar = tid >> 2, ac = (tid & 3) * 4;   // A tile load: row, kcol
    const int br = tid >> 4, bc = (tid & 15) * 4;  // B tile load

    float acc[4][4] = {};

    for (int k0 = 0; k0 < K; k0 += BKt) {
        float4 av;
        int arow = m0 + ar;
        if (arow < M) av = *(const float4*)(A + (size_t)arow * K + k0 + ac);
        else          av = make_float4(0.f, 0.f, 0.f, 0.f);
        As[ac + 0][ar] = av.x; As[ac + 1][ar] = av.y;
        As[ac + 2][ar] = av.z; As[ac + 3][ar] = av.w;
        *(float4*)&Bs[br][bc] = *(const float4*)(Bm + (size_t)(k0 + br) * N + n0 + bc);
        __syncthreads();
        #pragma unroll
        for (int kk = 0; kk < BKt; kk++) {
            float a[4], b[4];
            *(float4*)a = *(const float4*)&As[kk][ty * 4];
            *(float4*)b = *(const float4*)&Bs[kk][tx * 4];
            #pragma unroll
            for (int i = 0; i < 4; i++)
                #pragma unroll
                for (int j = 0; j < 4; j++)
                    acc[i][j] += a[i] * b[j];
        }
        __syncthreads();
    }
    #pragma unroll
    for (int i = 0; i < 4; i++) {
        int row = m0 + ty * 4 + i;
        if (row >= M) continue;
        #pragma unroll
        for (int j = 0; j < 4; j++) {
            int col = n0 + tx * 4 + j;
            float v = acc[i][j] + bias[col];
            if (RELU) v = fmaxf(v, 0.0f);
            C[(size_t)row * N + col] = v;
        }
    }
}

// ---------------------------------------------------------------------------
// Embed GEMM: mem[b, s, :] = relu( x[b, :, s] @ W_embed + b_embed )
// x: (B, 2048, 49).  A is the transposed view.  M=49 (padded to 64).
// grid = (N/64=12, B), 256 threads.
// ---------------------------------------------------------------------------
__global__ __launch_bounds__(256)
void embed_gemm(const float* __restrict__ X, const float* __restrict__ W,
                const float* __restrict__ bias, float* __restrict__ C)
{
    __shared__ float As[BKt][BM];   // As[kk][s]
    __shared__ float Bs[BKt][BN];
    const int tid = threadIdx.x;
    const int n0 = blockIdx.x * BN;
    const int b  = blockIdx.y;
    const int tx = tid & 15, ty = tid >> 4;
    const int br = tid >> 4, bc = (tid & 15) * 4;
    const float* Xb = X + (size_t)b * FDIM * SEQ;

    float acc[4][4] = {};

    for (int k0 = 0; k0 < FDIM; k0 += BKt) {
        #pragma unroll
        for (int i = 0; i < 4; i++) {
            int idx = tid + i * 256;           // 0..1023
            int kk = idx >> 6, s = idx & 63;
            As[kk][s] = (s < SEQ) ? Xb[(size_t)(k0 + kk) * SEQ + s] : 0.0f;
        }
        *(float4*)&Bs[br][bc] = *(const float4*)(W + (size_t)(k0 + br) * D + n0 + bc);
        __syncthreads();
        #pragma unroll
        for (int kk = 0; kk < BKt; kk++) {
            float a[4], bb[4];
            *(float4*)a  = *(const float4*)&As[kk][ty * 4];
            *(float4*)bb = *(const float4*)&Bs[kk][tx * 4];
            #pragma unroll
            for (int i = 0; i < 4; i++)
                #pragma unroll
                for (int j = 0; j < 4; j++)
                    acc[i][j] += a[i] * bb[j];
        }
        __syncthreads();
    }
    #pragma unroll
    for (int i = 0; i < 4; i++) {
        int s = ty * 4 + i;
        if (s >= SEQ) continue;
        #pragma unroll
        for (int j = 0; j < 4; j++) {
            int col = n0 + tx * 4 + j;
            float v = fmaxf(acc[i][j] + bias[col], 0.0f);
            C[((size_t)b * SEQ + s) * D + col] = v;
        }
    }
}

// ---------------------------------------------------------------------------
// tgt_ln = layernorm(2 * query_embed) * g1 + be1    (100 rows of 768)
// ---------------------------------------------------------------------------
__global__ __launch_bounds__(256)
void ln_query(const float* __restrict__ qe, const float* __restrict__ g,
              const float* __restrict__ be, float* __restrict__ out)
{
    __shared__ float sred[8];
    int r = blockIdx.x, t = threadIdx.x;
    float v[3];
    float s = 0.0f;
    #pragma unroll
    for (int i = 0; i < 3; i++) { v[i] = 2.0f * qe[(size_t)r * D + t + i * 256]; s += v[i]; }
    float mean = block_sum(s, sred) * (1.0f / D);
    float vs = 0.0f;
    #pragma unroll
    for (int i = 0; i < 3; i++) { float d = v[i] - mean; vs += d * d; }
    float var = block_sum(vs, sred) * (1.0f / D);
    float inv = rsqrtf(var + EPS);
    #pragma unroll
    for (int i = 0; i < 3; i++) {
        int c = t + i * 256;
        out[(size_t)r * D + c] = (v[i] - mean) * inv * g[c] + be[c];
    }
}

// ---------------------------------------------------------------------------
// out[r] = layernorm(res[rr] + inp[r]) * g + be ;  rr = bcast ? r%100 : r
// grid = B*KQ rows
// ---------------------------------------------------------------------------
__global__ __launch_bounds__(256)
void ln_residual(const float* __restrict__ res, const float* __restrict__ inp,
                 const float* __restrict__ g, const float* __restrict__ be,
                 float* __restrict__ out, int bcast)
{
    __shared__ float sred[8];
    long r = blockIdx.x;
    long rr = bcast ? (r % KQ) : r;
    int t = threadIdx.x;
    float v[3];
    float s = 0.0f;
    #pragma unroll
    for (int i = 0; i < 3; i++) {
        int c = t + i * 256;
        v[i] = res[rr * D + c] + inp[r * D + c];
        s += v[i];
    }
    float mean = block_sum(s, sred) * (1.0f / D);
    float vs = 0.0f;
    #pragma unroll
    for (int i = 0; i < 3; i++) { float d = v[i] - mean; vs += d * d; }
    float var = block_sum(vs, sred) * (1.0f / D);
    float inv = rsqrtf(var + EPS);
    #pragma unroll
    for (int i = 0; i < 3; i++) {
        int c = t + i * 256;
        out[r * D + c] = (v[i] - mean) * inv * g[c] + be[c];
    }
}

// ---------------------------------------------------------------------------
// Fused cross attention.  grid=(NHEAD, BATCH), 128 threads.
// Q (batch-independent): (100, 768); K,V: (B*49, 768).
// Each thread owns one query row: 49 scores -> softmax -> 96-dim context.
// ---------------------------------------------------------------------------
#define QPAD 97
__global__ __launch_bounds__(128)
void attn_kernel(const float* __restrict__ Q, const float* __restrict__ Kb,
                 const float* __restrict__ Vb, float* __restrict__ ctx)
{
    extern __shared__ float sm[];
    float* Qs = sm;                       // KQ * QPAD
    float* Ks = sm + KQ * QPAD;           // SEQ * HD
    float* Vs = Ks + SEQ * HD;            // SEQ * HD
    const int h = blockIdx.x, b = blockIdx.y;
    const int t = threadIdx.x;

    for (int idx = t; idx < KQ * HD; idx += 128) {
        int k = idx / HD, d = idx - k * HD;
        Qs[k * QPAD + d] = Q[(size_t)k * D + h * HD + d];
    }
    for (int idx = t; idx < SEQ * HD; idx += 128) {
        int s = idx / HD, d = idx - s * HD;
        size_t off = ((size_t)b * SEQ + s) * D + h * HD + d;
        Ks[idx] = Kb[off];
        Vs[idx] = Vb[off];
    }
    __syncthreads();

    if (t < KQ) {
        const float scale = 0.102062072615966f;   // 1/sqrt(96)
        float sc[SEQ];
        float mx = -1e30f;
        #pragma unroll 7
        for (int s = 0; s < SEQ; s++) {
            float a = 0.0f;
            const float* qp = Qs + t * QPAD;
            const float* kp = Ks + s * HD;
            #pragma unroll 8
            for (int d = 0; d < HD; d++) a += qp[d] * kp[d];
            a *= scale;
            sc[s] = a;
            mx = fmaxf(mx, a);
        }
        float sum = 0.0f;
        #pragma unroll 7
        for (int s = 0; s < SEQ; s++) { sc[s] = expf(sc[s] - mx); sum += sc[s]; }
        float inv = 1.0f / sum;
        float* op = ctx + ((size_t)b * KQ + t) * D + h * HD;
        #pragma unroll 8
        for (int d = 0; d < HD; d++) {
            float a = 0.0f;
            #pragma unroll 7
            for (int s = 0; s < SEQ; s++) a += sc[s] * Vs[s * HD + d];
            op[d] = a * inv;
        }
    }
}

// ---------------------------------------------------------------------------
// GroupFC: logits[b, k*10+g] = sum_d h[b,k,d] * dup_pool[k,d,g] + dup_bias
// grid = (KQ, BATCH), 256 threads
// ---------------------------------------------------------------------------
__global__ __launch_bounds__(256)
void groupfc(const float* __restrict__ H, const float* __restrict__ P,
             const float* __restrict__ db, float* __restrict__ out)
{
    const int k = blockIdx.x, b = blockIdx.y;
    const int t = threadIdx.x;
    float acc[GRP] = {};
    const float* hp = H + ((size_t)b * KQ + k) * D;
    const float* pp = P + (size_t)k * D * GRP;
    for (int d = t; d < D; d += 256) {
        float hv = hp[d];
        const float* q = pp + d * GRP;
        #pragma unroll
        for (int g = 0; g < GRP; g++) acc[g] += hv * q[g];
    }
    #pragma unroll
    for (int g = 0; g < GRP; g++)
        #pragma unroll
        for (int o = 16; o > 0; o >>= 1)
            acc[g] += __shfl_down_sync(0xffffffffu, acc[g], o);
    __shared__ float red[8][GRP];
    int w = t >> 5, lane = t & 31;
    if (lane == 0) {
        #pragma unroll
        for (int g = 0; g < GRP; g++) red[w][g] = acc[g];
    }
    __syncthreads();
    if (t < GRP) {
        float s = 0.0f;
        #pragma unroll
        for (int w2 = 0; w2 < 8; w2++) s += red[w2][t];
        out[(size_t)b * NC + k * GRP + t] = s + db[k * GRP + t];
    }
}

// ---------------------------------------------------------------------------
// Host launcher
// ---------------------------------------------------------------------------
static float* symaddr(const void* sym_dummy, const void* symbol) {
    (void)sym_dummy;
    void* p = nullptr;
    cudaGetSymbolAddress(&p, symbol);
    return (float*)p;
}

extern "C" void kernel_launch(void* const* d_in, const int* in_sizes, int n_in,
                              void* d_out, int out_size)
{
    (void)in_sizes; (void)n_in; (void)out_size;
    const float* x        = (const float*)d_in[0];
    const float* W_embed  = (const float*)d_in[1];
    const float* b_embed  = (const float*)d_in[2];
    const float* query_embed = (const float*)d_in[3];
    const float* wq = (const float*)d_in[4];
    const float* wk = (const float*)d_in[5];
    const float* wv = (const float*)d_in[6];
    const float* bq = (const float*)d_in[7];
    const float* bk = (const float*)d_in[8];
    const float* bv = (const float*)d_in[9];
    const float* wo = (const float*)d_in[10];
    const float* bo = (const float*)d_in[11];
    const float* w1 = (const float*)d_in[12];
    const float* b1 = (const float*)d_in[13];
    const float* w2 = (const float*)d_in[14];
    const float* b2 = (const float*)d_in[15];
    const float* g1 = (const float*)d_in[16];
    const float* be1= (const float*)d_in[17];
    const float* g2 = (const float*)d_in[18];
    const float* be2= (const float*)d_in[19];
    const float* g3 = (const float*)d_in[20];
    const float* be3= (const float*)d_in[21];
    const float* dup_pool = (const float*)d_in[22];
    const float* dup_bias = (const float*)d_in[23];
    float* out = (float*)d_out;

    float *mem, *kb, *vb, *tln, *qb, *ctx, *tmp, *tgt2, *h1, *h2, *hh;
    cudaGetSymbolAddress((void**)&mem,  g_mem);
    cudaGetSymbolAddress((void**)&kb,   g_kbuf);
    cudaGetSymbolAddress((void**)&vb,   g_vbuf);
    cudaGetSymbolAddress((void**)&tln,  g_tgtln);
    cudaGetSymbolAddress((void**)&qb,   g_q);
    cudaGetSymbolAddress((void**)&ctx,  g_ctx);
    cudaGetSymbolAddress((void**)&tmp,  g_tmp);
    cudaGetSymbolAddress((void**)&tgt2, g_tgt2);
    cudaGetSymbolAddress((void**)&h1,   g_h1);
    cudaGetSymbolAddress((void**)&h2,   g_h2);
    cudaGetSymbolAddress((void**)&hh,   g_h);

    const int BKQ = BATCH * KQ;     // 12800
    const int BS  = BATCH * SEQ;    // 6272

    // 1) embed: mem = relu(x^T @ W_embed + b_embed)
    embed_gemm<<<dim3(D / BN, BATCH), 256>>>(x, W_embed, b_embed, mem);

    // 2) tgt_ln = LN(2 * query_embed)
    ln_query<<<KQ, 256>>>(query_embed, g1, be1, tln);

    // 3) q = tgt_ln @ wq + bq   (batch independent, 100x768)
    sgemm<false><<<dim3(D / BN, (KQ + BM - 1) / BM), 256>>>(tln, wq, bq, qb, KQ, D, D);

    // 4) k, v projections (6272 x 768)
    sgemm<false><<<dim3(D / BN, BS / BM), 256>>>(mem, wk, bk, kb, BS, D, D);
    sgemm<false><<<dim3(D / BN, BS / BM), 256>>>(mem, wv, bv, vb, BS, D, D);

    // 5) attention
    {
        int smem = (KQ * QPAD + 2 * SEQ * HD) * (int)sizeof(float);  // 76432
        cudaFuncSetAttribute(attn_kernel, cudaFuncAttributeMaxDynamicSharedMemorySize, smem);
        attn_kernel<<<dim3(NHEAD, BATCH), 128, smem>>>(qb, kb, vb, ctx);
    }

    // 6) attn_out = ctx @ wo + bo
    sgemm<false><<<dim3(D / BN, BKQ / BM), 256>>>(ctx, wo, bo, tmp, BKQ, D, D);

    // 7) tgt2 = LN(tgt_ln + attn_out)
    ln_residual<<<BKQ, 256>>>(tln, tmp, g2, be2, tgt2, 1);

    // 8) FFN
    sgemm<true ><<<dim3(FF / BN, BKQ / BM), 256>>>(tgt2, w1, b1, h1, BKQ, FF, D);
    sgemm<false><<<dim3(D / BN, BKQ / BM), 256>>>(h1, w2, b2, h2, BKQ, D, FF);

    // 9) h = LN(tgt2 + ffn)
    ln_residual<<<BKQ, 256>>>(tgt2, h2, g3, be3, hh, 0);

    // 10) group FC -> logits
    groupfc<<<dim3(KQ, BATCH), 256>>>(hh, dup_pool, dup_bias, out);
}

// round 2
// speedup vs baseline: 2.1250x; 2.1250x over previous
#include <cuda_runtime.h>
#include <cuda_bf16.h>
#include <math.h>
#include <stdint.h>

// ---------------------------------------------------------------------------
// Problem constants
// ---------------------------------------------------------------------------
#define BATCH 128
#define SEQ   49
#define FDIM  2048
#define D     768
#define KQ    100
#define NHEAD 8
#define HD    96
#define FF    2048
#define NC    1000
#define GRP   10
#define EPS   1e-5f

// ---------------------------------------------------------------------------
// Scratch (static device globals; no allocation allowed)
// ---------------------------------------------------------------------------
// bf16 hi/lo split buffers (A operands / weights)
__device__ __nv_bfloat16 g_xT_hi [BATCH * SEQ * FDIM];
__device__ __nv_bfloat16 g_xT_lo [BATCH * SEQ * FDIM];
__device__ __nv_bfloat16 g_mem_hi[BATCH * SEQ * D];
__device__ __nv_bfloat16 g_mem_lo[BATCH * SEQ * D];
__device__ __nv_bfloat16 g_ctx_hi[BATCH * KQ * D];
__device__ __nv_bfloat16 g_ctx_lo[BATCH * KQ * D];
__device__ __nv_bfloat16 g_t2_hi [BATCH * KQ * D];
__device__ __nv_bfloat16 g_t2_lo [BATCH * KQ * D];
__device__ __nv_bfloat16 g_h1_hi [BATCH * KQ * FF];
__device__ __nv_bfloat16 g_h1_lo [BATCH * KQ * FF];
// weights hi/lo
__device__ __nv_bfloat16 g_We_hi[FDIM * D], g_We_lo[FDIM * D];
__device__ __nv_bfloat16 g_wk_hi[D * D],    g_wk_lo[D * D];
__device__ __nv_bfloat16 g_wv_hi[D * D],    g_wv_lo[D * D];
__device__ __nv_bfloat16 g_wo_hi[D * D],    g_wo_lo[D * D];
__device__ __nv_bfloat16 g_w1_hi[D * FF],   g_w1_lo[D * FF];
__device__ __nv_bfloat16 g_w2_hi[FF * D],   g_w2_lo[FF * D];
// fp32 buffers
__device__ float g_kbuf [BATCH * SEQ * D];
__device__ float g_vbuf [BATCH * SEQ * D];
__device__ float g_tgtln[KQ * D];
__device__ float g_q    [KQ * D];
__device__ float g_tmp  [BATCH * KQ * D];
__device__ float g_tgt2 [BATCH * KQ * D];
__device__ float g_h2   [BATCH * KQ * D];
__device__ float g_h    [BATCH * KQ * D];

// ---------------------------------------------------------------------------
// PTX helpers
// ---------------------------------------------------------------------------
__device__ __forceinline__ uint32_t smem_u32(const void* p) {
    return (uint32_t)__cvta_generic_to_shared(p);
}
__device__ __forceinline__ void ldsm_x4(uint32_t* d, uint32_t addr) {
    asm volatile("ldmatrix.sync.aligned.m8n8.x4.shared.b16 {%0,%1,%2,%3}, [%4];"
        : "=r"(d[0]), "=r"(d[1]), "=r"(d[2]), "=r"(d[3]) : "r"(addr));
}
__device__ __forceinline__ void ldsm_x4t(uint32_t* d, uint32_t addr) {
    asm volatile("ldmatrix.sync.aligned.m8n8.x4.trans.shared.b16 {%0,%1,%2,%3}, [%4];"
        : "=r"(d[0]), "=r"(d[1]), "=r"(d[2]), "=r"(d[3]) : "r"(addr));
}
__device__ __forceinline__ void mma16816(float* c, const uint32_t* a, const uint32_t* b) {
    asm volatile("mma.sync.aligned.m16n8k16.row.col.f32.bf16.bf16.f32 "
        "{%0,%1,%2,%3}, {%4,%5,%6,%7}, {%8,%9}, {%0,%1,%2,%3};"
        : "+f"(c[0]), "+f"(c[1]), "+f"(c[2]), "+f"(c[3])
        : "r"(a[0]), "r"(a[1]), "r"(a[2]), "r"(a[3]), "r"(b[0]), "r"(b[1]));
}

// ---------------------------------------------------------------------------
// Tensor-core GEMM: C[M,N] = split_bf16(A[M,K]) @ split_bf16(B[K,N]) + bias
// 3-term split: hi*hi + hi*lo + lo*hi  (~fp32-ish accuracy)
// BM=128, BN=64, BK=32; 256 threads; warps 4(M) x 2(N), warp tile 32x32.
// M, K multiples of 32/128 as used; N multiple of 64.
// ---------------------------------------------------------------------------
#define TBM 128
#define TBN 64
#define TBK 32
#define APAD 8
#define BPAD 8
#define A_STRIDE (TBK + APAD)   // 40 bf16 (80 B) per row
#define B_STRIDE (TBN + BPAD)   // 72 bf16 (144 B) per row
#define A_BUF (TBM * A_STRIDE)  // 5120 elems
#define B_BUF (TBK * B_STRIDE)  // 2304 elems

template<bool RELU, bool WF32, bool WHILO>
__global__ __launch_bounds__(256)
void mma_gemm(const __nv_bfloat16* __restrict__ Ah, const __nv_bfloat16* __restrict__ Al,
              const __nv_bfloat16* __restrict__ Bh, const __nv_bfloat16* __restrict__ Bl,
              const float* __restrict__ bias,
              float* __restrict__ Cf, __nv_bfloat16* __restrict__ Chi,
              __nv_bfloat16* __restrict__ Clo,
              int M, int N, int K)
{
    extern __shared__ __align__(16) unsigned char smem_raw[];
    __nv_bfloat16* sAh = (__nv_bfloat16*)smem_raw;       // [2][TBM][A_STRIDE]
    __nv_bfloat16* sAl = sAh + 2 * A_BUF;
    __nv_bfloat16* sBh = sAl + 2 * A_BUF;                // [2][TBK][B_STRIDE]
    __nv_bfloat16* sBl = sBh + 2 * B_BUF;

    const int tid  = threadIdx.x;
    const int n0   = blockIdx.x * TBN;
    const int m0   = blockIdx.y * TBM;
    const int lane = tid & 31;
    const int warp = tid >> 5;
    const int wm   = warp & 3;          // 0..3
    const int wn   = warp >> 2;         // 0..1
    const int m_base = wm * 32;
    const int n_base = wn * 32;

    // gmem staging indices
    const int ar  = tid >> 2;           // 0..63 (rows ar, ar+64)
    const int ac8 = (tid & 3) * 8;      // k-col (bf16 elems)
    const int br  = tid >> 3;           // 0..31
    const int bc8 = (tid & 7) * 8;

    const uint32_t uAh = smem_u32(sAh), uAl = smem_u32(sAl);
    const uint32_t uBh = smem_u32(sBh), uBl = smem_u32(sBl);

    float acc[2][4][4];
    #pragma unroll
    for (int i = 0; i < 2; i++)
        #pragma unroll
        for (int j = 0; j < 4; j++)
            #pragma unroll
            for (int k = 0; k < 4; k++) acc[i][j][k] = 0.0f;

    uint4 ra_h0, ra_h1, ra_l0, ra_l1, rb_h, rb_l;

    auto gload = [&](int k0) {
        const __nv_bfloat16* pa = Ah + (size_t)(m0 + ar) * K + k0 + ac8;
        ra_h0 = *(const uint4*)pa;
        ra_h1 = *(const uint4*)(pa + (size_t)64 * K);
        const __nv_bfloat16* pl = Al + (size_t)(m0 + ar) * K + k0 + ac8;
        ra_l0 = *(const uint4*)pl;
        ra_l1 = *(const uint4*)(pl + (size_t)64 * K);
        rb_h  = *(const uint4*)(Bh + (size_t)(k0 + br) * N + n0 + bc8);
        rb_l  = *(const uint4*)(Bl + (size_t)(k0 + br) * N + n0 + bc8);
    };
    auto sstore = [&](int buf) {
        __nv_bfloat16* a0 = sAh + buf * A_BUF + ar * A_STRIDE + ac8;
        *(uint4*)a0 = ra_h0;
        *(uint4*)(a0 + 64 * A_STRIDE) = ra_h1;
        __nv_bfloat16* a1 = sAl + buf * A_BUF + ar * A_STRIDE + ac8;
        *(uint4*)a1 = ra_l0;
        *(uint4*)(a1 + 64 * A_STRIDE) = ra_l1;
        *(uint4*)(sBh + buf * B_BUF + br * B_STRIDE + bc8) = rb_h;
        *(uint4*)(sBl + buf * B_BUF + br * B_STRIDE + bc8) = rb_l;
    };

    const int lr = lane & 15;           // row within 16-tile
    const int lc = lane >> 4;           // 0/1 -> col half (8 elems)

    auto compute = [&](int buf) {
        #pragma unroll
        for (int kk = 0; kk < TBK; kk += 16) {
            uint32_t a_hi[2][4], a_lo[2][4], b_hi[2][4], b_lo[2][4];
            #pragma unroll
            for (int mt = 0; mt < 2; mt++) {
                uint32_t off = (uint32_t)((buf * A_BUF +
                    (m_base + mt * 16 + lr) * A_STRIDE + kk + lc * 8) * 2);
                ldsm_x4(a_hi[mt], uAh + off);
                ldsm_x4(a_lo[mt], uAl + off);
            }
            #pragma unroll
            for (int ng = 0; ng < 2; ng++) {
                uint32_t off = (uint32_t)((buf * B_BUF +
                    (kk + lr) * B_STRIDE + n_base + ng * 16 + lc * 8) * 2);
                ldsm_x4t(b_hi[ng], uBh + off);
                ldsm_x4t(b_lo[ng], uBl + off);
            }
            #pragma unroll
            for (int mt = 0; mt < 2; mt++)
                #pragma unroll
                for (int ng = 0; ng < 2; ng++)
                    #pragma unroll
                    for (int h = 0; h < 2; h++) {
                        float* c = acc[mt][ng * 2 + h];
                        mma16816(c, a_hi[mt], &b_hi[ng][2 * h]);
                        mma16816(c, a_hi[mt], &b_lo[ng][2 * h]);
                        mma16816(c, a_lo[mt], &b_hi[ng][2 * h]);
                    }
        }
    };

    const int niter = K / TBK;
    gload(0);
    sstore(0);
    __syncthreads();
    for (int it = 0; it < niter; it++) {
        int cur = it & 1;
        if (it + 1 < niter) gload((it + 1) * TBK);
        compute(cur);
        if (it + 1 < niter) sstore(cur ^ 1);
        __syncthreads();
    }

    // epilogue
    #pragma unroll
    for (int mt = 0; mt < 2; mt++) {
        int r0 = m0 + m_base + mt * 16 + (lane >> 2);
        #pragma unroll
        for (int j = 0; j < 4; j++) {
            int col = n0 + n_base + j * 8 + (lane & 3) * 2;
            float bx = bias[col], by = bias[col + 1];
            float* c = acc[mt][j];
            float v00 = c[0] + bx, v01 = c[1] + by;   // row r0
            float v10 = c[2] + bx, v11 = c[3] + by;   // row r0+8
            if (RELU) {
                v00 = fmaxf(v00, 0.f); v01 = fmaxf(v01, 0.f);
                v10 = fmaxf(v10, 0.f); v11 = fmaxf(v11, 0.f);
            }
            if (WF32) {
                *(float2*)(Cf + (size_t)r0 * N + col)       = make_float2(v00, v01);
                *(float2*)(Cf + (size_t)(r0 + 8) * N + col) = make_float2(v10, v11);
            }
            if (WHILO) {
                __nv_bfloat16 h00 = __float2bfloat16(v00), h01 = __float2bfloat16(v01);
                __nv_bfloat16 h10 = __float2bfloat16(v10), h11 = __float2bfloat16(v11);
                __nv_bfloat162 p0; p0.x = h00; p0.y = h01;
                __nv_bfloat162 p1; p1.x = h10; p1.y = h11;
                *(__nv_bfloat162*)(Chi + (size_t)r0 * N + col)       = p0;
                *(__nv_bfloat162*)(Chi + (size_t)(r0 + 8) * N + col) = p1;
                __nv_bfloat162 q0, q1;
                q0.x = __float2bfloat16(v00 - __bfloat162float(h00));
                q0.y = __float2bfloat16(v01 - __bfloat162float(h01));
                q1.x = __float2bfloat16(v10 - __bfloat162float(h10));
                q1.y = __float2bfloat16(v11 - __bfloat162float(h11));
                *(__nv_bfloat162*)(Clo + (size_t)r0 * N + col)       = q0;
                *(__nv_bfloat162*)(Clo + (size_t)(r0 + 8) * N + col) = q1;
            }
        }
    }
}

// ---------------------------------------------------------------------------
// Transpose + hi/lo convert: x (B, FDIM, SEQ) -> A (B*SEQ, FDIM)
// ---------------------------------------------------------------------------
__global__ __launch_bounds__(256)
void xT_cvt(const float* __restrict__ x, __nv_bfloat16* __restrict__ hi,
            __nv_bfloat16* __restrict__ lo)
{
    __shared__ float t[32][33];
    int b = blockIdx.z;
    int f0 = blockIdx.x * 32, s0 = blockIdx.y * 32;
    const float* xb = x + (size_t)b * FDIM * SEQ;
    int tx = threadIdx.x, ty = threadIdx.y;
    #pragma unroll
    for (int i = ty; i < 32; i += 8) {
        int s = s0 + tx;
        t[i][tx] = (s < SEQ) ? xb[(size_t)(f0 + i) * SEQ + s] : 0.f;
    }
    __syncthreads();
    #pragma unroll
    for (int i = ty; i < 32; i += 8) {
        int s = s0 + i, f = f0 + tx;
        if (s < SEQ) {
            float v = t[tx][i];
            __nv_bfloat16 h = __float2bfloat16(v);
            size_t o = ((size_t)b * SEQ + s) * FDIM + f;
            hi[o] = h;
            lo[o] = __float2bfloat16(v - __bfloat162float(h));
        }
    }
}

// ---------------------------------------------------------------------------
// fp32 -> bf16 hi/lo elementwise
// ---------------------------------------------------------------------------
__global__ __launch_bounds__(256)
void cvt_hilo(const float* __restrict__ in, __nv_bfloat16* __restrict__ hi,
              __nv_bfloat16* __restrict__ lo, int n)
{
    int i = blockIdx.x * 256 + threadIdx.x;
    if (i < n) {
        float v = in[i];
        __nv_bfloat16 h = __float2bfloat16(v);
        hi[i] = h;
        lo[i] = __float2bfloat16(v - __bfloat162float(h));
    }
}

// ---------------------------------------------------------------------------
// Block reduction helper
// ---------------------------------------------------------------------------
__device__ __forceinline__ float block_sum(float v, float* sred) {
    int lane = threadIdx.x & 31, w = threadIdx.x >> 5;
    #pragma unroll
    for (int o = 16; o > 0; o >>= 1) v += __shfl_down_sync(0xffffffffu, v, o);
    if (lane == 0) sred[w] = v;
    __syncthreads();
    float s = (threadIdx.x < 8) ? sred[threadIdx.x] : 0.0f;
    if (w == 0) {
        #pragma unroll
        for (int o = 4; o > 0; o >>= 1) s += __shfl_down_sync(0xffffffffu, s, o);
        if (lane == 0) sred[0] = s;
    }
    __syncthreads();
    float r = sred[0];
    __syncthreads();
    return r;
}

// ---------------------------------------------------------------------------
// fp32 SGEMM (kept for tiny q projection, M=100)
// ---------------------------------------------------------------------------
#define BM 64
#define BN 64
#define BKt 16
__global__ __launch_bounds__(256)
void sgemm(const float* __restrict__ A, const float* __restrict__ Bm,
           const float* __restrict__ bias, float* __restrict__ C,
           int M, int N, int K)
{
    __shared__ float As[BKt][BM];
    __shared__ float Bs[BKt][BN];
    const int tid = threadIdx.x;
    const int n0 = blockIdx.x * BN;
    const int m0 = blockIdx.y * BM;
    const int tx = tid & 15, ty = tid >> 4;
    const int ar = tid >> 2, ac = (tid & 3) * 4;
    const int br = tid >> 4, bc = (tid & 15) * 4;
    float acc[4][4] = {};
    for (int k0 = 0; k0 < K; k0 += BKt) {
        float4 av;
        int arow = m0 + ar;
        if (arow < M) av = *(const float4*)(A + (size_t)arow * K + k0 + ac);
        else          av = make_float4(0.f, 0.f, 0.f, 0.f);
        As[ac + 0][ar] = av.x; As[ac + 1][ar] = av.y;
        As[ac + 2][ar] = av.z; As[ac + 3][ar] = av.w;
        *(float4*)&Bs[br][bc] = *(const float4*)(Bm + (size_t)(k0 + br) * N + n0 + bc);
        __syncthreads();
        #pragma unroll
        for (int kk = 0; kk < BKt; kk++) {
            float a[4], b[4];
            *(float4*)a = *(const float4*)&As[kk][ty * 4];
            *(float4*)b = *(const float4*)&Bs[kk][tx * 4];
            #pragma unroll
            for (int i = 0; i < 4; i++)
                #pragma unroll
                for (int j = 0; j < 4; j++)
                    acc[i][j] += a[i] * b[j];
        }
        __syncthreads();
    }
    #pragma unroll
    for (int i = 0; i < 4; i++) {
        int row = m0 + ty * 4 + i;
        if (row >= M) continue;
        #pragma unroll
        for (int j = 0; j < 4; j++) {
            int col = n0 + tx * 4 + j;
            C[(size_t)row * N + col] = acc[i][j] + bias[col];
        }
    }
}

// ---------------------------------------------------------------------------
// tgt_ln = layernorm(2 * query_embed) * g1 + be1
// ---------------------------------------------------------------------------
__global__ __launch_bounds__(256)
void ln_query(const float* __restrict__ qe, const float* __restrict__ g,
              const float* __restrict__ be, float* __restrict__ out)
{
    __shared__ float sred[8];
    int r = blockIdx.x, t = threadIdx.x;
    float v[3];
    float s = 0.0f;
    #pragma unroll
    for (int i = 0; i < 3; i++) { v[i] = 2.0f * qe[(size_t)r * D + t + i * 256]; s += v[i]; }
    float mean = block_sum(s, sred) * (1.0f / D);
    float vs = 0.0f;
    #pragma unroll
    for (int i = 0; i < 3; i++) { float d = v[i] - mean; vs += d * d; }
    float var = block_sum(vs, sred) * (1.0f / D);
    float inv = rsqrtf(var + EPS);
    #pragma unroll
    for (int i = 0; i < 3; i++) {
        int c = t + i * 256;
        out[(size_t)r * D + c] = (v[i] - mean) * inv * g[c] + be[c];
    }
}

// ---------------------------------------------------------------------------
// out = LN(res[rr] + inp[r]) ; optional bf16 hi/lo copies
// ---------------------------------------------------------------------------
__global__ __launch_bounds__(256)
void ln_residual(const float* __restrict__ res, const float* __restrict__ inp,
                 const float* __restrict__ g, const float* __restrict__ be,
                 float* __restrict__ out, __nv_bfloat16* __restrict__ ohi,
                 __nv_bfloat16* __restrict__ olo, int bcast)
{
    __shared__ float sred[8];
    long r = blockIdx.x;
    long rr = bcast ? (r % KQ) : r;
    int t = threadIdx.x;
    float v[3];
    float s = 0.0f;
    #pragma unroll
    for (int i = 0; i < 3; i++) {
        int c = t + i * 256;
        v[i] = res[rr * D + c] + inp[r * D + c];
        s += v[i];
    }
    float mean = block_sum(s, sred) * (1.0f / D);
    float vs = 0.0f;
    #pragma unroll
    for (int i = 0; i < 3; i++) { float d = v[i] - mean; vs += d * d; }
    float var = block_sum(vs, sred) * (1.0f / D);
    float inv = rsqrtf(var + EPS);
    #pragma unroll
    for (int i = 0; i < 3; i++) {
        int c = t + i * 256;
        float o = (v[i] - mean) * inv * g[c] + be[c];
        out[r * D + c] = o;
        if (ohi) {
            __nv_bfloat16 h = __float2bfloat16(o);
            ohi[r * D + c] = h;
            olo[r * D + c] = __float2bfloat16(o - __bfloat162float(h));
        }
    }
}

// ---------------------------------------------------------------------------
// Fused cross attention. grid=(NHEAD, BATCH), 128 threads.
// Writes ctx directly as bf16 hi/lo (feeds attn-out GEMM).
// ---------------------------------------------------------------------------
#define QPAD 97
__global__ __launch_bounds__(128)
void attn_kernel(const float* __restrict__ Q, const float* __restrict__ Kb,
                 const float* __restrict__ Vb,
                 __nv_bfloat16* __restrict__ chi, __nv_bfloat16* __restrict__ clo)
{
    extern __shared__ float sm[];
    float* Qs = sm;
    float* Ks = sm + KQ * QPAD;
    float* Vs = Ks + SEQ * HD;
    const int hh = blockIdx.x, b = blockIdx.y;
    const int t = threadIdx.x;

    for (int idx = t; idx < KQ * HD; idx += 128) {
        int k = idx / HD, d = idx - k * HD;
        Qs[k * QPAD + d] = Q[(size_t)k * D + hh * HD + d];
    }
    for (int idx = t; idx < SEQ * HD; idx += 128) {
        int s = idx / HD, d = idx - s * HD;
        size_t off = ((size_t)b * SEQ + s) * D + hh * HD + d;
        Ks[idx] = Kb[off];
        Vs[idx] = Vb[off];
    }
    __syncthreads();

    if (t < KQ) {
        const float scale = 0.102062072615966f;   // 1/sqrt(96)
        float sc[SEQ];
        float mx = -1e30f;
        #pragma unroll 7
        for (int s = 0; s < SEQ; s++) {
            float a = 0.0f;
            const float* qp = Qs + t * QPAD;
            const float* kp = Ks + s * HD;
            #pragma unroll 8
            for (int d = 0; d < HD; d++) a += qp[d] * kp[d];
            a *= scale;
            sc[s] = a;
            mx = fmaxf(mx, a);
        }
        float sum = 0.0f;
        #pragma unroll 7
        for (int s = 0; s < SEQ; s++) { sc[s] = expf(sc[s] - mx); sum += sc[s]; }
        float inv = 1.0f / sum;
        size_t ob = ((size_t)b * KQ + t) * D + hh * HD;
        #pragma unroll 8
        for (int d = 0; d < HD; d++) {
            float a = 0.0f;
            #pragma unroll 7
            for (int s = 0; s < SEQ; s++) a += sc[s] * Vs[s * HD + d];
            float val = a * inv;
            __nv_bfloat16 h = __float2bfloat16(val);
            chi[ob + d] = h;
            clo[ob + d] = __float2bfloat16(val - __bfloat162float(h));
        }
    }
}

// ---------------------------------------------------------------------------
// GroupFC
// ---------------------------------------------------------------------------
__global__ __launch_bounds__(256)
void groupfc(const float* __restrict__ H, const float* __restrict__ P,
             const float* __restrict__ db, float* __restrict__ out)
{
    const int k = blockIdx.x, b = blockIdx.y;
    const int t = threadIdx.x;
    float acc[GRP] = {};
    const float* hp = H + ((size_t)b * KQ + k) * D;
    const float* pp = P + (size_t)k * D * GRP;
    for (int d = t; d < D; d += 256) {
        float hv = hp[d];
        const float* q = pp + d * GRP;
        #pragma unroll
        for (int g = 0; g < GRP; g++) acc[g] += hv * q[g];
    }
    #pragma unroll
    for (int g = 0; g < GRP; g++)
        #pragma unroll
        for (int o = 16; o > 0; o >>= 1)
            acc[g] += __shfl_down_sync(0xffffffffu, acc[g], o);
    __shared__ float red[8][GRP];
    int w = t >> 5, lane = t & 31;
    if (lane == 0) {
        #pragma unroll
        for (int g = 0; g < GRP; g++) red[w][g] = acc[g];
    }
    __syncthreads();
    if (t < GRP) {
        float s = 0.0f;
        #pragma unroll
        for (int w2 = 0; w2 < 8; w2++) s += red[w2][t];
        out[(size_t)b * NC + k * GRP + t] = s + db[k * GRP + t];
    }
}

// ---------------------------------------------------------------------------
// Host launcher
// ---------------------------------------------------------------------------
extern "C" void kernel_launch(void* const* d_in, const int* in_sizes, int n_in,
                              void* d_out, int out_size)
{
    (void)in_sizes; (void)n_in; (void)out_size;
    const float* x        = (const float*)d_in[0];
    const float* W_embed  = (const float*)d_in[1];
    const float* b_embed  = (const float*)d_in[2];
    const float* query_embed = (const float*)d_in[3];
    const float* wq = (const float*)d_in[4];
    const float* wk = (const float*)d_in[5];
    const float* wv = (const float*)d_in[6];
    const float* bq = (const float*)d_in[7];
    const float* bk = (const float*)d_in[8];
    const float* bv = (const float*)d_in[9];
    const float* wo = (const float*)d_in[10];
    const float* bo = (const float*)d_in[11];
    const float* w1 = (const float*)d_in[12];
    const float* b1 = (const float*)d_in[13];
    const float* w2 = (const float*)d_in[14];
    const float* b2 = (const float*)d_in[15];
    const float* g1 = (const float*)d_in[16];
    const float* be1= (const float*)d_in[17];
    const float* g2 = (const float*)d_in[18];
    const float* be2= (const float*)d_in[19];
    const float* g3 = (const float*)d_in[20];
    const float* be3= (const float*)d_in[21];
    const float* dup_pool = (const float*)d_in[22];
    const float* dup_bias = (const float*)d_in[23];
    float* out = (float*)d_out;

    __nv_bfloat16 *xTh, *xTl, *memh, *meml, *ctxh, *ctxl, *t2h, *t2l, *h1h, *h1l;
    __nv_bfloat16 *Weh, *Wel, *wkh, *wkl, *wvh, *wvl, *woh, *wol, *w1h, *w1l, *w2h, *w2l;
    float *kb, *vb, *tln, *qb, *tmp, *tgt2, *h2, *hhp;
    cudaGetSymbolAddress((void**)&xTh,  g_xT_hi);  cudaGetSymbolAddress((void**)&xTl,  g_xT_lo);
    cudaGetSymbolAddress((void**)&memh, g_mem_hi); cudaGetSymbolAddress((void**)&meml, g_mem_lo);
    cudaGetSymbolAddress((void**)&ctxh, g_ctx_hi); cudaGetSymbolAddress((void**)&ctxl, g_ctx_lo);
    cudaGetSymbolAddress((void**)&t2h,  g_t2_hi);  cudaGetSymbolAddress((void**)&t2l,  g_t2_lo);
    cudaGetSymbolAddress((void**)&h1h,  g_h1_hi);  cudaGetSymbolAddress((void**)&h1l,  g_h1_lo);
    cudaGetSymbolAddress((void**)&Weh,  g_We_hi);  cudaGetSymbolAddress((void**)&Wel,  g_We_lo);
    cudaGetSymbolAddress((void**)&wkh,  g_wk_hi);  cudaGetSymbolAddress((void**)&wkl,  g_wk_lo);
    cudaGetSymbolAddress((void**)&wvh,  g_wv_hi);  cudaGetSymbolAddress((void**)&wvl,  g_wv_lo);
    cudaGetSymbolAddress((void**)&woh,  g_wo_hi);  cudaGetSymbolAddress((void**)&wol,  g_wo_lo);
    cudaGetSymbolAddress((void**)&w1h,  g_w1_hi);  cudaGetSymbolAddress((void**)&w1l,  g_w1_lo);
    cudaGetSymbolAddress((void**)&w2h,  g_w2_hi);  cudaGetSymbolAddress((void**)&w2l,  g_w2_lo);
    cudaGetSymbolAddress((void**)&kb,   g_kbuf);
    cudaGetSymbolAddress((void**)&vb,   g_vbuf);
    cudaGetSymbolAddress((void**)&tln,  g_tgtln);
    cudaGetSymbolAddress((void**)&qb,   g_q);
    cudaGetSymbolAddress((void**)&tmp,  g_tmp);
    cudaGetSymbolAddress((void**)&tgt2, g_tgt2);
    cudaGetSymbolAddress((void**)&h2,   g_h2);
    cudaGetSymbolAddress((void**)&hhp,  g_h);

    const int BKQ = BATCH * KQ;     // 12800
    const int BS  = BATCH * SEQ;    // 6272
    const int SMEM_GEMM = (2 * A_BUF * 2 + 2 * B_BUF * 2) * (int)sizeof(__nv_bfloat16);

    static bool attr_set = false;
    if (!attr_set) {
        cudaFuncSetAttribute(mma_gemm<true,  false, true >, cudaFuncAttributeMaxDynamicSharedMemorySize, SMEM_GEMM);
        cudaFuncSetAttribute(mma_gemm<false, true,  false>, cudaFuncAttributeMaxDynamicSharedMemorySize, SMEM_GEMM);
        int smem_attn = (KQ * QPAD + 2 * SEQ * HD) * (int)sizeof(float);
        cudaFuncSetAttribute(attn_kernel, cudaFuncAttributeMaxDynamicSharedMemorySize, smem_attn);
        attr_set = true;
    }

    // 0) conversions
    xT_cvt<<<dim3(FDIM / 32, 2, BATCH), dim3(32, 8)>>>(x, xTh, xTl);
    cvt_hilo<<<(FDIM * D + 255) / 256, 256>>>(W_embed, Weh, Wel, FDIM * D);
    cvt_hilo<<<(D * D + 255) / 256, 256>>>(wk, wkh, wkl, D * D);
    cvt_hilo<<<(D * D + 255) / 256, 256>>>(wv, wvh, wvl, D * D);
    cvt_hilo<<<(D * D + 255) / 256, 256>>>(wo, woh, wol, D * D);
    cvt_hilo<<<(D * FF + 255) / 256, 256>>>(w1, w1h, w1l, D * FF);
    cvt_hilo<<<(FF * D + 255) / 256, 256>>>(w2, w2h, w2l, FF * D);

    // 1) embed: mem = relu(xT @ W_embed + b_embed)  -> bf16 hi/lo
    mma_gemm<true, false, true><<<dim3(D / TBN, BS / TBM), 256, SMEM_GEMM>>>(
        xTh, xTl, Weh, Wel, b_embed, nullptr, memh, meml, BS, D, FDIM);

    // 2) tgt_ln = LN(2 * query_embed)
    ln_query<<<KQ, 256>>>(query_embed, g1, be1, tln);

    // 3) q = tgt_ln @ wq + bq (tiny, fp32)
    sgemm<<<dim3(D / BN, (KQ + BM - 1) / BM), 256>>>(tln, wq, bq, qb, KQ, D, D);

    // 4) k, v projections -> fp32
    mma_gemm<false, true, false><<<dim3(D / TBN, BS / TBM), 256, SMEM_GEMM>>>(
        memh, meml, wkh, wkl, bk, kb, nullptr, nullptr, BS, D, D);
    mma_gemm<false, true, false><<<dim3(D / TBN, BS / TBM), 256, SMEM_GEMM>>>(
        memh, meml, wvh, wvl, bv, vb, nullptr, nullptr, BS, D, D);

    // 5) attention -> ctx bf16 hi/lo
    {
        int smem = (KQ * QPAD + 2 * SEQ * HD) * (int)sizeof(float);
        attn_kernel<<<dim3(NHEAD, BATCH), 128, smem>>>(qb, kb, vb, ctxh, ctxl);
    }

    // 6) attn_out = ctx @ wo + bo -> fp32
    mma_gemm<false, true, false><<<dim3(D / TBN, BKQ / TBM), 256, SMEM_GEMM>>>(
        ctxh, ctxl, woh, wol, bo, tmp, nullptr, nullptr, BKQ, D, D);

    // 7) tgt2 = LN(tgt_ln + attn_out) -> fp32 + bf16 hi/lo
    ln_residual<<<BKQ, 256>>>(tln, tmp, g2, be2, tgt2, t2h, t2l, 1);

    // 8) FFN
    mma_gemm<true, false, true><<<dim3(FF / TBN, BKQ / TBM), 256, SMEM_GEMM>>>(
        t2h, t2l, w1h, w1l, b1, nullptr, h1h, h1l, BKQ, FF, D);
    mma_gemm<false, true, false><<<dim3(D / TBN, BKQ / TBM), 256, SMEM_GEMM>>>(
        h1h, h1l, w2h, w2l, b2, h2, nullptr, nullptr, BKQ, D, FF);

    // 9) h = LN(tgt2 + ffn)
    ln_residual<<<BKQ, 256>>>(tgt2, h2, g3, be3, hhp, nullptr, nullptr, 0);

    // 10) group FC -> logits
    groupfc<<<dim3(KQ, BATCH), 256>>>(hhp, dup_pool, dup_bias, out);
}

// round 3
// speedup vs baseline: 2.8017x; 1.3184x over previous
#include <cuda_runtime.h>
#include <cuda_fp16.h>
#include <math.h>
#include <stdint.h>

// ---------------------------------------------------------------------------
// Problem constants
// ---------------------------------------------------------------------------
#define BATCH 128
#define SEQ   49
#define FDIM  2048
#define D     768
#define KQ    100
#define NHEAD 8
#define HD    96
#define FF    2048
#define NC    1000
#define GRP   10
#define EPS   1e-5f

// ---------------------------------------------------------------------------
// Scratch (static device globals; no allocation allowed)
// ---------------------------------------------------------------------------
// fp16 activation buffers (A operands)
__device__ __half g_xT  [BATCH * SEQ * FDIM];
__device__ __half g_memh[BATCH * SEQ * D];
__device__ __half g_ctxh[BATCH * KQ * D];
__device__ __half g_t2h [BATCH * KQ * D];
__device__ __half g_h1h [BATCH * KQ * FF];
// fp16 weight hi/lo split buffers (B operands)
__device__ __half g_We_hi[FDIM * D], g_We_lo[FDIM * D];
__device__ __half g_wk_hi[D * D],    g_wk_lo[D * D];
__device__ __half g_wv_hi[D * D],    g_wv_lo[D * D];
__device__ __half g_wo_hi[D * D],    g_wo_lo[D * D];
__device__ __half g_w1_hi[D * FF],   g_w1_lo[D * FF];
__device__ __half g_w2_hi[FF * D],   g_w2_lo[FF * D];
// fp32 buffers
__device__ float g_kbuf [BATCH * SEQ * D];
__device__ float g_vbuf [BATCH * SEQ * D];
__device__ float g_tgtln[KQ * D];
__device__ float g_q    [KQ * D];
__device__ float g_tmp  [BATCH * KQ * D];
__device__ float g_tgt2 [BATCH * KQ * D];
__device__ float g_h2   [BATCH * KQ * D];
__device__ float g_h    [BATCH * KQ * D];

// ---------------------------------------------------------------------------
// PTX helpers
// ---------------------------------------------------------------------------
__device__ __forceinline__ uint32_t smem_u32(const void* p) {
    return (uint32_t)__cvta_generic_to_shared(p);
}
__device__ __forceinline__ void ldsm_x4(uint32_t* d, uint32_t addr) {
    asm volatile("ldmatrix.sync.aligned.m8n8.x4.shared.b16 {%0,%1,%2,%3}, [%4];"
        : "=r"(d[0]), "=r"(d[1]), "=r"(d[2]), "=r"(d[3]) : "r"(addr));
}
__device__ __forceinline__ void ldsm_x4t(uint32_t* d, uint32_t addr) {
    asm volatile("ldmatrix.sync.aligned.m8n8.x4.trans.shared.b16 {%0,%1,%2,%3}, [%4];"
        : "=r"(d[0]), "=r"(d[1]), "=r"(d[2]), "=r"(d[3]) : "r"(addr));
}
__device__ __forceinline__ void mma16816h(float* c, const uint32_t* a, const uint32_t* b) {
    asm volatile("mma.sync.aligned.m16n8k16.row.col.f32.f16.f16.f32 "
        "{%0,%1,%2,%3}, {%4,%5,%6,%7}, {%8,%9}, {%0,%1,%2,%3};"
        : "+f"(c[0]), "+f"(c[1]), "+f"(c[2]), "+f"(c[3])
        : "r"(a[0]), "r"(a[1]), "r"(a[2]), "r"(a[3]), "r"(b[0]), "r"(b[1]));
}

// ---------------------------------------------------------------------------
// Tensor-core GEMM: C[M,N] = A_fp16[M,K] @ (B_hi + B_lo)[K,N] + bias
// A is plain fp16; B split into fp16 hi/lo -> 2 MMAs per tile.
// BM=128, BN=64, BK=32; 256 threads; warps 4(M) x 2(N), warp tile 32x32.
// ---------------------------------------------------------------------------
#define TBM 128
#define TBN 64
#define TBK 32
#define APAD 8
#define BPAD 8
#define A_STRIDE (TBK + APAD)   // 40
#define B_STRIDE (TBN + BPAD)   // 72
#define A_BUF (TBM * A_STRIDE)  // 5120 elems
#define B_BUF (TBK * B_STRIDE)  // 2304 elems

template<bool RELU, bool WF32, bool WHALF>
__global__ __launch_bounds__(256)
void mma_gemm(const __half* __restrict__ A,
              const __half* __restrict__ Bh, const __half* __restrict__ Bl,
              const float* __restrict__ bias,
              float* __restrict__ Cf, __half* __restrict__ Ch,
              int M, int N, int K)
{
    extern __shared__ __align__(16) unsigned char smem_raw[];
    __half* sA  = (__half*)smem_raw;          // [2][TBM][A_STRIDE]
    __half* sBh = sA + 2 * A_BUF;             // [2][TBK][B_STRIDE]
    __half* sBl = sBh + 2 * B_BUF;

    const int tid  = threadIdx.x;
    const int n0   = blockIdx.x * TBN;
    const int m0   = blockIdx.y * TBM;
    const int lane = tid & 31;
    const int warp = tid >> 5;
    const int wm   = warp & 3;
    const int wn   = warp >> 2;
    const int m_base = wm * 32;
    const int n_base = wn * 32;

    const int ar  = tid >> 2;           // 0..63 (rows ar, ar+64)
    const int ac8 = (tid & 3) * 8;
    const int br  = tid >> 3;           // 0..31
    const int bc8 = (tid & 7) * 8;

    const uint32_t uA  = smem_u32(sA);
    const uint32_t uBh = smem_u32(sBh), uBl = smem_u32(sBl);

    float acc[2][4][4];
    #pragma unroll
    for (int i = 0; i < 2; i++)
        #pragma unroll
        for (int j = 0; j < 4; j++)
            #pragma unroll
            for (int k = 0; k < 4; k++) acc[i][j][k] = 0.0f;

    uint4 ra0, ra1, rb_h, rb_l;

    auto gload = [&](int k0) {
        const __half* pa = A + (size_t)(m0 + ar) * K + k0 + ac8;
        ra0 = *(const uint4*)pa;
        ra1 = *(const uint4*)(pa + (size_t)64 * K);
        rb_h = *(const uint4*)(Bh + (size_t)(k0 + br) * N + n0 + bc8);
        rb_l = *(const uint4*)(Bl + (size_t)(k0 + br) * N + n0 + bc8);
    };
    auto sstore = [&](int buf) {
        __half* a0 = sA + buf * A_BUF + ar * A_STRIDE + ac8;
        *(uint4*)a0 = ra0;
        *(uint4*)(a0 + 64 * A_STRIDE) = ra1;
        *(uint4*)(sBh + buf * B_BUF + br * B_STRIDE + bc8) = rb_h;
        *(uint4*)(sBl + buf * B_BUF + br * B_STRIDE + bc8) = rb_l;
    };

    const int lr = lane & 15;
    const int lc = lane >> 4;

    auto compute = [&](int buf) {
        #pragma unroll
        for (int kk = 0; kk < TBK; kk += 16) {
            uint32_t a[2][4], b_hi[2][4], b_lo[2][4];
            #pragma unroll
            for (int mt = 0; mt < 2; mt++) {
                uint32_t off = (uint32_t)((buf * A_BUF +
                    (m_base + mt * 16 + lr) * A_STRIDE + kk + lc * 8) * 2);
                ldsm_x4(a[mt], uA + off);
            }
            #pragma unroll
            for (int ng = 0; ng < 2; ng++) {
                uint32_t off = (uint32_t)((buf * B_BUF +
                    (kk + lr) * B_STRIDE + n_base + ng * 16 + lc * 8) * 2);
                ldsm_x4t(b_hi[ng], uBh + off);
                ldsm_x4t(b_lo[ng], uBl + off);
            }
            #pragma unroll
            for (int mt = 0; mt < 2; mt++)
                #pragma unroll
                for (int ng = 0; ng < 2; ng++)
                    #pragma unroll
                    for (int h = 0; h < 2; h++) {
                        float* c = acc[mt][ng * 2 + h];
                        mma16816h(c, a[mt], &b_hi[ng][2 * h]);
                        mma16816h(c, a[mt], &b_lo[ng][2 * h]);
                    }
        }
    };

    const int niter = K / TBK;
    gload(0);
    sstore(0);
    __syncthreads();
    for (int it = 0; it < niter; it++) {
        int cur = it & 1;
        if (it + 1 < niter) gload((it + 1) * TBK);
        compute(cur);
        if (it + 1 < niter) sstore(cur ^ 1);
        __syncthreads();
    }

    // epilogue
    #pragma unroll
    for (int mt = 0; mt < 2; mt++) {
        int r0 = m0 + m_base + mt * 16 + (lane >> 2);
        #pragma unroll
        for (int j = 0; j < 4; j++) {
            int col = n0 + n_base + j * 8 + (lane & 3) * 2;
            float bx = bias[col], by = bias[col + 1];
            float* c = acc[mt][j];
            float v00 = c[0] + bx, v01 = c[1] + by;
            float v10 = c[2] + bx, v11 = c[3] + by;
            if (RELU) {
                v00 = fmaxf(v00, 0.f); v01 = fmaxf(v01, 0.f);
                v10 = fmaxf(v10, 0.f); v11 = fmaxf(v11, 0.f);
            }
            if (WF32) {
                *(float2*)(Cf + (size_t)r0 * N + col)       = make_float2(v00, v01);
                *(float2*)(Cf + (size_t)(r0 + 8) * N + col) = make_float2(v10, v11);
            }
            if (WHALF) {
                __half2 p0; p0.x = __float2half_rn(v00); p0.y = __float2half_rn(v01);
                __half2 p1; p1.x = __float2half_rn(v10); p1.y = __float2half_rn(v11);
                *(__half2*)(Ch + (size_t)r0 * N + col)       = p0;
                *(__half2*)(Ch + (size_t)(r0 + 8) * N + col) = p1;
            }
        }
    }
}

// ---------------------------------------------------------------------------
// Transpose + fp16 convert: x (B, FDIM, SEQ) -> A (B*SEQ, FDIM)
// ---------------------------------------------------------------------------
__global__ __launch_bounds__(256)
void xT_cvt(const float* __restrict__ x, __half* __restrict__ o)
{
    __shared__ float t[32][33];
    int b = blockIdx.z;
    int f0 = blockIdx.x * 32, s0 = blockIdx.y * 32;
    const float* xb = x + (size_t)b * FDIM * SEQ;
    int tx = threadIdx.x, ty = threadIdx.y;
    #pragma unroll
    for (int i = ty; i < 32; i += 8) {
        int s = s0 + tx;
        t[i][tx] = (s < SEQ) ? xb[(size_t)(f0 + i) * SEQ + s] : 0.f;
    }
    __syncthreads();
    #pragma unroll
    for (int i = ty; i < 32; i += 8) {
        int s = s0 + i, f = f0 + tx;
        if (s < SEQ)
            o[((size_t)b * SEQ + s) * FDIM + f] = __float2half_rn(t[tx][i]);
    }
}

// ---------------------------------------------------------------------------
// fp32 -> fp16 hi/lo elementwise (weights), 4-wide
// ---------------------------------------------------------------------------
__global__ __launch_bounds__(256)
void cvt_hilo(const float* __restrict__ in, __half* __restrict__ hi,
              __half* __restrict__ lo, int n4)
{
    int i = blockIdx.x * 256 + threadIdx.x;
    if (i < n4) {
        float4 v = ((const float4*)in)[i];
        __half2 h0, h1, l0, l1;
        h0.x = __float2half_rn(v.x); h0.y = __float2half_rn(v.y);
        h1.x = __float2half_rn(v.z); h1.y = __float2half_rn(v.w);
        l0.x = __float2half_rn(v.x - __half2float(h0.x));
        l0.y = __float2half_rn(v.y - __half2float(h0.y));
        l1.x = __float2half_rn(v.z - __half2float(h1.x));
        l1.y = __float2half_rn(v.w - __half2float(h1.y));
        ((__half2*)hi)[i * 2]     = h0;
        ((__half2*)hi)[i * 2 + 1] = h1;
        ((__half2*)lo)[i * 2]     = l0;
        ((__half2*)lo)[i * 2 + 1] = l1;
    }
}

// ---------------------------------------------------------------------------
// Block reduction helper
// ---------------------------------------------------------------------------
__device__ __forceinline__ float block_sum(float v, float* sred) {
    int lane = threadIdx.x & 31, w = threadIdx.x >> 5;
    #pragma unroll
    for (int o = 16; o > 0; o >>= 1) v += __shfl_down_sync(0xffffffffu, v, o);
    if (lane == 0) sred[w] = v;
    __syncthreads();
    float s = (threadIdx.x < 8) ? sred[threadIdx.x] : 0.0f;
    if (w == 0) {
        #pragma unroll
        for (int o = 4; o > 0; o >>= 1) s += __shfl_down_sync(0xffffffffu, s, o);
        if (lane == 0) sred[0] = s;
    }
    __syncthreads();
    float r = sred[0];
    __syncthreads();
    return r;
}

// ---------------------------------------------------------------------------
// fp32 SGEMM (tiny q projection, M=100) — exact
// ---------------------------------------------------------------------------
#define BM 64
#define BN 64
#define BKt 16
__global__ __launch_bounds__(256)
void sgemm(const float* __restrict__ A, const float* __restrict__ Bm,
           const float* __restrict__ bias, float* __restrict__ C,
           int M, int N, int K)
{
    __shared__ float As[BKt][BM];
    __shared__ float Bs[BKt][BN];
    const int tid = threadIdx.x;
    const int n0 = blockIdx.x * BN;
    const int m0 = blockIdx.y * BM;
    const int tx = tid & 15, ty = tid >> 4;
    const int ar = tid >> 2, ac = (tid & 3) * 4;
    const int br = tid >> 4, bc = (tid & 15) * 4;
    float acc[4][4] = {};
    for (int k0 = 0; k0 < K; k0 += BKt) {
        float4 av;
        int arow = m0 + ar;
        if (arow < M) av = *(const float4*)(A + (size_t)arow * K + k0 + ac);
        else          av = make_float4(0.f, 0.f, 0.f, 0.f);
        As[ac + 0][ar] = av.x; As[ac + 1][ar] = av.y;
        As[ac + 2][ar] = av.z; As[ac + 3][ar] = av.w;
        *(float4*)&Bs[br][bc] = *(const float4*)(Bm + (size_t)(k0 + br) * N + n0 + bc);
        __syncthreads();
        #pragma unroll
        for (int kk = 0; kk < BKt; kk++) {
            float a[4], b[4];
            *(float4*)a = *(const float4*)&As[kk][ty * 4];
            *(float4*)b = *(const float4*)&Bs[kk][tx * 4];
            #pragma unroll
            for (int i = 0; i < 4; i++)
                #pragma unroll
                for (int j = 0; j < 4; j++)
                    acc[i][j] += a[i] * b[j];
        }
        __syncthreads();
    }
    #pragma unroll
    for (int i = 0; i < 4; i++) {
        int row = m0 + ty * 4 + i;
        if (row >= M) continue;
        #pragma unroll
        for (int j = 0; j < 4; j++) {
            int col = n0 + tx * 4 + j;
            C[(size_t)row * N + col] = acc[i][j] + bias[col];
        }
    }
}

// ---------------------------------------------------------------------------
// tgt_ln = layernorm(2 * query_embed) * g1 + be1
// ---------------------------------------------------------------------------
__global__ __launch_bounds__(256)
void ln_query(const float* __restrict__ qe, const float* __restrict__ g,
              const float* __restrict__ be, float* __restrict__ out)
{
    __shared__ float sred[8];
    int r = blockIdx.x, t = threadIdx.x;
    float v[3];
    float s = 0.0f;
    #pragma unroll
    for (int i = 0; i < 3; i++) { v[i] = 2.0f * qe[(size_t)r * D + t + i * 256]; s += v[i]; }
    float mean = block_sum(s, sred) * (1.0f / D);
    float vs = 0.0f;
    #pragma unroll
    for (int i = 0; i < 3; i++) { float d = v[i] - mean; vs += d * d; }
    float var = block_sum(vs, sred) * (1.0f / D);
    float inv = rsqrtf(var + EPS);
    #pragma unroll
    for (int i = 0; i < 3; i++) {
        int c = t + i * 256;
        out[(size_t)r * D + c] = (v[i] - mean) * inv * g[c] + be[c];
    }
}

// ---------------------------------------------------------------------------
// out = LN(res[rr] + inp[r]) ; optional fp16 copy
// ---------------------------------------------------------------------------
__global__ __launch_bounds__(256)
void ln_residual(const float* __restrict__ res, const float* __restrict__ inp,
                 const float* __restrict__ g, const float* __restrict__ be,
                 float* __restrict__ out, __half* __restrict__ oh, int bcast)
{
    __shared__ float sred[8];
    long r = blockIdx.x;
    long rr = bcast ? (r % KQ) : r;
    int t = threadIdx.x;
    float v[3];
    float s = 0.0f;
    #pragma unroll
    for (int i = 0; i < 3; i++) {
        int c = t + i * 256;
        v[i] = res[rr * D + c] + inp[r * D + c];
        s += v[i];
    }
    float mean = block_sum(s, sred) * (1.0f / D);
    float vs = 0.0f;
    #pragma unroll
    for (int i = 0; i < 3; i++) { float d = v[i] - mean; vs += d * d; }
    float var = block_sum(vs, sred) * (1.0f / D);
    float inv = rsqrtf(var + EPS);
    #pragma unroll
    for (int i = 0; i < 3; i++) {
        int c = t + i * 256;
        float o = (v[i] - mean) * inv * g[c] + be[c];
        out[r * D + c] = o;
        if (oh) oh[r * D + c] = __float2half_rn(o);
    }
}

// ---------------------------------------------------------------------------
// Fused cross attention. grid=(NHEAD, BATCH), 128 threads. Writes fp16 ctx.
// ---------------------------------------------------------------------------
#define QPAD 97
__global__ __launch_bounds__(128)
void attn_kernel(const float* __restrict__ Q, const float* __restrict__ Kb,
                 const float* __restrict__ Vb, __half* __restrict__ ch)
{
    extern __shared__ float sm[];
    float* Qs = sm;
    float* Ks = sm + KQ * QPAD;
    float* Vs = Ks + SEQ * HD;
    const int hh = blockIdx.x, b = blockIdx.y;
    const int t = threadIdx.x;

    for (int idx = t; idx < KQ * HD; idx += 128) {
        int k = idx / HD, d = idx - k * HD;
        Qs[k * QPAD + d] = Q[(size_t)k * D + hh * HD + d];
    }
    for (int idx = t; idx < SEQ * HD; idx += 128) {
        int s = idx / HD, d = idx - s * HD;
        size_t off = ((size_t)b * SEQ + s) * D + hh * HD + d;
        Ks[idx] = Kb[off];
        Vs[idx] = Vb[off];
    }
    __syncthreads();

    if (t < KQ) {
        const float scale = 0.102062072615966f;   // 1/sqrt(96)
        float sc[SEQ];
        float mx = -1e30f;
        #pragma unroll 7
        for (int s = 0; s < SEQ; s++) {
            float a = 0.0f;
            const float* qp = Qs + t * QPAD;
            const float* kp = Ks + s * HD;
            #pragma unroll 8
            for (int d = 0; d < HD; d++) a += qp[d] * kp[d];
            a *= scale;
            sc[s] = a;
            mx = fmaxf(mx, a);
        }
        float sum = 0.0f;
        #pragma unroll 7
        for (int s = 0; s < SEQ; s++) { sc[s] = expf(sc[s] - mx); sum += sc[s]; }
        float inv = 1.0f / sum;
        size_t ob = ((size_t)b * KQ + t) * D + hh * HD;
        #pragma unroll 8
        for (int d = 0; d < HD; d++) {
            float a = 0.0f;
            #pragma unroll 7
            for (int s = 0; s < SEQ; s++) a += sc[s] * Vs[s * HD + d];
            ch[ob + d] = __float2half_rn(a * inv);
        }
    }
}

// ---------------------------------------------------------------------------
// GroupFC
// ---------------------------------------------------------------------------
__global__ __launch_bounds__(256)
void groupfc(const float* __restrict__ H, const float* __restrict__ P,
             const float* __restrict__ db, float* __restrict__ out)
{
    const int k = blockIdx.x, b = blockIdx.y;
    const int t = threadIdx.x;
    float acc[GRP] = {};
    const float* hp = H + ((size_t)b * KQ + k) * D;
    const float* pp = P + (size_t)k * D * GRP;
    for (int d = t; d < D; d += 256) {
        float hv = hp[d];
        const float* q = pp + d * GRP;
        #pragma unroll
        for (int g = 0; g < GRP; g++) acc[g] += hv * q[g];
    }
    #pragma unroll
    for (int g = 0; g < GRP; g++)
        #pragma unroll
        for (int o = 16; o > 0; o >>= 1)
            acc[g] += __shfl_down_sync(0xffffffffu, acc[g], o);
    __shared__ float red[8][GRP];
    int w = t >> 5, lane = t & 31;
    if (lane == 0) {
        #pragma unroll
        for (int g = 0; g < GRP; g++) red[w][g] = acc[g];
    }
    __syncthreads();
    if (t < GRP) {
        float s = 0.0f;
        #pragma unroll
        for (int w2 = 0; w2 < 8; w2++) s += red[w2][t];
        out[(size_t)b * NC + k * GRP + t] = s + db[k * GRP + t];
    }
}

// ---------------------------------------------------------------------------
// Host launcher
// ---------------------------------------------------------------------------
extern "C" void kernel_launch(void* const* d_in, const int* in_sizes, int n_in,
                              void* d_out, int out_size)
{
    (void)in_sizes; (void)n_in; (void)out_size;
    const float* x        = (const float*)d_in[0];
    const float* W_embed  = (const float*)d_in[1];
    const float* b_embed  = (const float*)d_in[2];
    const float* query_embed = (const float*)d_in[3];
    const float* wq = (const float*)d_in[4];
    const float* wk = (const float*)d_in[5];
    const float* wv = (const float*)d_in[6];
    const float* bq = (const float*)d_in[7];
    const float* bk = (const float*)d_in[8];
    const float* bv = (const float*)d_in[9];
    const float* wo = (const float*)d_in[10];
    const float* bo = (const float*)d_in[11];
    const float* w1 = (const float*)d_in[12];
    const float* b1 = (const float*)d_in[13];
    const float* w2 = (const float*)d_in[14];
    const float* b2 = (const float*)d_in[15];
    const float* g1 = (const float*)d_in[16];
    const float* be1= (const float*)d_in[17];
    const float* g2 = (const float*)d_in[18];
    const float* be2= (const float*)d_in[19];
    const float* g3 = (const float*)d_in[20];
    const float* be3= (const float*)d_in[21];
    const float* dup_pool = (const float*)d_in[22];
    const float* dup_bias = (const float*)d_in[23];
    float* out = (float*)d_out;

    __half *xT, *memh, *ctxh, *t2h, *h1h;
    __half *Weh, *Wel, *wkh, *wkl, *wvh, *wvl, *woh, *wol, *w1h, *w1l, *w2h, *w2l;
    float *kb, *vb, *tln, *qb, *tmp, *tgt2, *h2, *hhp;
    cudaGetSymbolAddress((void**)&xT,   g_xT);
    cudaGetSymbolAddress((void**)&memh, g_memh);
    cudaGetSymbolAddress((void**)&ctxh, g_ctxh);
    cudaGetSymbolAddress((void**)&t2h,  g_t2h);
    cudaGetSymbolAddress((void**)&h1h,  g_h1h);
    cudaGetSymbolAddress((void**)&Weh,  g_We_hi);  cudaGetSymbolAddress((void**)&Wel,  g_We_lo);
    cudaGetSymbolAddress((void**)&wkh,  g_wk_hi);  cudaGetSymbolAddress((void**)&wkl,  g_wk_lo);
    cudaGetSymbolAddress((void**)&wvh,  g_wv_hi);  cudaGetSymbolAddress((void**)&wvl,  g_wv_lo);
    cudaGetSymbolAddress((void**)&woh,  g_wo_hi);  cudaGetSymbolAddress((void**)&wol,  g_wo_lo);
    cudaGetSymbolAddress((void**)&w1h,  g_w1_hi);  cudaGetSymbolAddress((void**)&w1l,  g_w1_lo);
    cudaGetSymbolAddress((void**)&w2h,  g_w2_hi);  cudaGetSymbolAddress((void**)&w2l,  g_w2_lo);
    cudaGetSymbolAddress((void**)&kb,   g_kbuf);
    cudaGetSymbolAddress((void**)&vb,   g_vbuf);
    cudaGetSymbolAddress((void**)&tln,  g_tgtln);
    cudaGetSymbolAddress((void**)&qb,   g_q);
    cudaGetSymbolAddress((void**)&tmp,  g_tmp);
    cudaGetSymbolAddress((void**)&tgt2, g_tgt2);
    cudaGetSymbolAddress((void**)&h2,   g_h2);
    cudaGetSymbolAddress((void**)&hhp,  g_h);

    const int BKQ = BATCH * KQ;     // 12800
    const int BS  = BATCH * SEQ;    // 6272
    const int SMEM_GEMM = (2 * A_BUF + 4 * B_BUF) * (int)sizeof(__half);  // 38912 B

    static bool attr_set = false;
    if (!attr_set) {
        cudaFuncSetAttribute(mma_gemm<true,  false, true >, cudaFuncAttributeMaxDynamicSharedMemorySize, SMEM_GEMM);
        cudaFuncSetAttribute(mma_gemm<false, true,  false>, cudaFuncAttributeMaxDynamicSharedMemorySize, SMEM_GEMM);
        int smem_attn = (KQ * QPAD + 2 * SEQ * HD) * (int)sizeof(float);
        cudaFuncSetAttribute(attn_kernel, cudaFuncAttributeMaxDynamicSharedMemorySize, smem_attn);
        attr_set = true;
    }

    // 0) conversions
    xT_cvt<<<dim3(FDIM / 32, 2, BATCH), dim3(32, 8)>>>(x, xT);
    cvt_hilo<<<(FDIM * D / 4 + 255) / 256, 256>>>(W_embed, Weh, Wel, FDIM * D / 4);
    cvt_hilo<<<(D * D / 4 + 255) / 256, 256>>>(wk, wkh, wkl, D * D / 4);
    cvt_hilo<<<(D * D / 4 + 255) / 256, 256>>>(wv, wvh, wvl, D * D / 4);
    cvt_hilo<<<(D * D / 4 + 255) / 256, 256>>>(wo, woh, wol, D * D / 4);
    cvt_hilo<<<(D * FF / 4 + 255) / 256, 256>>>(w1, w1h, w1l, D * FF / 4);
    cvt_hilo<<<(FF * D / 4 + 255) / 256, 256>>>(w2, w2h, w2l, FF * D / 4);

    // 1) embed: mem = relu(xT @ W_embed + b_embed)  -> fp16
    mma_gemm<true, false, true><<<dim3(D / TBN, BS / TBM), 256, SMEM_GEMM>>>(
        xT, Weh, Wel, b_embed, nullptr, memh, BS, D, FDIM);

    // 2) tgt_ln = LN(2 * query_embed)
    ln_query<<<KQ, 256>>>(query_embed, g1, be1, tln);

    // 3) q = tgt_ln @ wq + bq (tiny, fp32 exact)
    sgemm<<<dim3(D / BN, (KQ + BM - 1) / BM), 256>>>(tln, wq, bq, qb, KQ, D, D);

    // 4) k, v projections -> fp32
    mma_gemm<false, true, false><<<dim3(D / TBN, BS / TBM), 256, SMEM_GEMM>>>(
        memh, wkh, wkl, bk, kb, nullptr, BS, D, D);
    mma_gemm<false, true, false><<<dim3(D / TBN, BS / TBM), 256, SMEM_GEMM>>>(
        memh, wvh, wvl, bv, vb, nullptr, BS, D, D);

    // 5) attention -> ctx fp16
    {
        int smem = (KQ * QPAD + 2 * SEQ * HD) * (int)sizeof(float);
        attn_kernel<<<dim3(NHEAD, BATCH), 128, smem>>>(qb, kb, vb, ctxh);
    }

    // 6) attn_out = ctx @ wo + bo -> fp32
    mma_gemm<false, true, false><<<dim3(D / TBN, BKQ / TBM), 256, SMEM_GEMM>>>(
        ctxh, woh, wol, bo, tmp, nullptr, BKQ, D, D);

    // 7) tgt2 = LN(tgt_ln + attn_out) -> fp32 + fp16
    ln_residual<<<BKQ, 256>>>(tln, tmp, g2, be2, tgt2, t2h, 1);

    // 8) FFN
    mma_gemm<true, false, true><<<dim3(FF / TBN, BKQ / TBM), 256, SMEM_GEMM>>>(
        t2h, w1h, w1l, b1, nullptr, h1h, BKQ, FF, D);
    mma_gemm<false, true, false><<<dim3(D / TBN, BKQ / TBM), 256, SMEM_GEMM>>>(
        h1h, w2h, w2l, b2, h2, nullptr, BKQ, D, FF);

    // 9) h = LN(tgt2 + ffn)
    ln_residual<<<BKQ, 256>>>(tgt2, h2, g3, be3, hhp, nullptr, 0);

    // 10) group FC -> logits
    groupfc<<<dim3(KQ, BATCH), 256>>>(hhp, dup_pool, dup_bias, out);
}

// round 5
// speedup vs baseline: 3.0241x; 1.0794x over previous
#include <cuda_runtime.h>
#include <cuda_fp16.h>
#include <math.h>
#include <stdint.h>

// ---------------------------------------------------------------------------
// Problem constants
// ---------------------------------------------------------------------------
#define BATCH 128
#define SEQ   49
#define FDIM  2048
#define D     768
#define KQ    100
#define NHEAD 8
#define HD    96
#define FF    2048
#define NC    1000
#define GRP   10
#define EPS   1e-5f

// ---------------------------------------------------------------------------
// Scratch (static device globals; no allocation allowed)
// ---------------------------------------------------------------------------
// fp16 activation buffers (A operands, row-major [M, K])
__device__ __half g_xT  [BATCH * SEQ * FDIM];
__device__ __half g_memh[BATCH * SEQ * D];
__device__ __half g_ctxh[BATCH * KQ * D];
__device__ __half g_t2h [BATCH * KQ * D];
__device__ __half g_h1h [BATCH * KQ * FF];
// fp16 weight hi/lo split buffers (B operands, [K, N] row-major)
__device__ __half g_We_hi[FDIM * D], g_We_lo[FDIM * D];
__device__ __half g_wk_hi[D * D],    g_wk_lo[D * D];
__device__ __half g_wv_hi[D * D],    g_wv_lo[D * D];
__device__ __half g_wo_hi[D * D],    g_wo_lo[D * D];
__device__ __half g_w1_hi[D * FF],   g_w1_lo[D * FF];
__device__ __half g_w2_hi[FF * D],   g_w2_lo[FF * D];
// fp32 buffers
__device__ float g_kbuf [BATCH * SEQ * D];
__device__ float g_vbuf [BATCH * SEQ * D];
__device__ float g_tgtln[KQ * D];
__device__ float g_q    [KQ * D];
__device__ float g_tmp  [BATCH * KQ * D];
__device__ float g_tgt2 [BATCH * KQ * D];
__device__ float g_h2   [BATCH * KQ * D];
__device__ float g_h    [BATCH * KQ * D];

// ---------------------------------------------------------------------------
// PTX helpers
// ---------------------------------------------------------------------------
__device__ __forceinline__ uint32_t smem_u32(const void* p) {
    return (uint32_t)__cvta_generic_to_shared(p);
}
__device__ __forceinline__ void ldsm_x4(uint32_t* d, uint32_t addr) {
    asm volatile("ldmatrix.sync.aligned.m8n8.x4.shared.b16 {%0,%1,%2,%3}, [%4];"
        : "=r"(d[0]), "=r"(d[1]), "=r"(d[2]), "=r"(d[3]) : "r"(addr));
}
__device__ __forceinline__ void ldsm_x4t(uint32_t* d, uint32_t addr) {
    asm volatile("ldmatrix.sync.aligned.m8n8.x4.trans.shared.b16 {%0,%1,%2,%3}, [%4];"
        : "=r"(d[0]), "=r"(d[1]), "=r"(d[2]), "=r"(d[3]) : "r"(addr));
}
__device__ __forceinline__ void mma16816h(float* c, const uint32_t* a, const uint32_t* b) {
    asm volatile("mma.sync.aligned.m16n8k16.row.col.f32.f16.f16.f32 "
        "{%0,%1,%2,%3}, {%4,%5,%6,%7}, {%8,%9}, {%0,%1,%2,%3};"
        : "+f"(c[0]), "+f"(c[1]), "+f"(c[2]), "+f"(c[3])
        : "r"(a[0]), "r"(a[1]), "r"(a[2]), "r"(a[3]), "r"(b[0]), "r"(b[1]));
}
__device__ __forceinline__ void cp_async16(uint32_t dst, const void* src) {
    asm volatile("cp.async.cg.shared.global [%0], [%1], 16;"
        :: "r"(dst), "l"(src) : "memory");
}
__device__ __forceinline__ void cp_commit() {
    asm volatile("cp.async.commit_group;" ::: "memory");
}
template<int N_>
__device__ __forceinline__ void cp_wait() {
    asm volatile("cp.async.wait_group %0;" :: "n"(N_) : "memory");
}

// ---------------------------------------------------------------------------
// Tensor-core GEMM: C[M,N] = A_fp16[M,K] @ (B_hi + B_lo)[K,N] + bias
// CTA tile 128x128, BK=32, 256 threads (8 warps: 2 in M x 4 in N),
// warp tile 64x32 -> 32 MMAs per 8 ldmatrix per k16. cp.async double buffer.
// Requires: M % 128 == 0, N % 128 == 0, K % 32 == 0.
// ---------------------------------------------------------------------------
#define TBM 128
#define TBN 128
#define TBK 32
#define A_STRIDE (TBK + 8)      // 40 halfs
#define B_STRIDE (TBN + 8)      // 136 halfs
#define A_BUF (TBM * A_STRIDE)  // 5120 halfs
#define B_BUF (TBK * B_STRIDE)  // 4352 halfs
#define STAGE_HALFS (A_BUF + 2 * B_BUF)          // 13824
#define SMEM_GEMM (2 * STAGE_HALFS * 2)          // 55296 B

template<bool RELU, bool WF32, bool WHALF>
__global__ __launch_bounds__(256)
void mma_gemm(const __half* __restrict__ A,
              const __half* __restrict__ Bh, const __half* __restrict__ Bl,
              const float* __restrict__ bias,
              float* __restrict__ Cf, __half* __restrict__ Ch,
              int M, int N, int K)
{
    extern __shared__ __align__(16) unsigned char smem_raw[];
    __half* sA  = (__half*)smem_raw;              // [2][A_BUF]
    __half* sBh = sA + 2 * A_BUF;                 // [2][B_BUF]
    __half* sBl = sBh + 2 * B_BUF;                // [2][B_BUF]

    const int tid  = threadIdx.x;
    const int n0   = blockIdx.x * TBN;
    const int m0   = blockIdx.y * TBM;
    const int lane = tid & 31;
    const int warp = tid >> 5;
    const int m_base = (warp & 1) * 64;           // 2 warps in M
    const int n_base = (warp >> 1) * 32;          // 4 warps in N

    // load mapping
    const int ar = tid >> 2,  ac = (tid & 3) * 8;    // A: 2 iters of 128r x 32c
    const int br = tid >> 4,  bc = (tid & 15) * 8;   // B: 2 iters of 32r x 128c

    const uint32_t uA  = smem_u32(sA);
    const uint32_t uBh = smem_u32(sBh), uBl = smem_u32(sBl);

    float acc[4][4][4];
    #pragma unroll
    for (int i = 0; i < 4; i++)
        #pragma unroll
        for (int j = 0; j < 4; j++)
            #pragma unroll
            for (int k = 0; k < 4; k++) acc[i][j][k] = 0.0f;

    auto load_async = [&](int it, int buf) {
        const int k0 = it * TBK;
        // A: 128 x 32 halfs = 512 x 16B, 2 per thread
        uint32_t dA = uA + (uint32_t)((buf * A_BUF + ar * A_STRIDE + ac) * 2);
        const __half* gA = A + (size_t)(m0 + ar) * K + k0 + ac;
        cp_async16(dA, gA);
        cp_async16(dA + (uint32_t)(64 * A_STRIDE * 2), gA + (size_t)64 * K);
        // B hi/lo: 32 x 128 halfs = 512 x 16B each, 2 per thread each
        uint32_t off0 = (uint32_t)((buf * B_BUF + br * B_STRIDE + bc) * 2);
        uint32_t off1 = off0 + (uint32_t)(16 * B_STRIDE * 2);
        size_t g0 = (size_t)(k0 + br) * N + n0 + bc;
        size_t g1 = g0 + (size_t)16 * N;
        cp_async16(uBh + off0, Bh + g0);
        cp_async16(uBh + off1, Bh + g1);
        cp_async16(uBl + off0, Bl + g0);
        cp_async16(uBl + off1, Bl + g1);
    };

    const int lr = lane & 15;
    const int lc = lane >> 4;

    auto compute = [&](int buf) {
        #pragma unroll
        for (int kk = 0; kk < TBK; kk += 16) {
            uint32_t a[4][4], b_hi[2][4], b_lo[2][4];
            #pragma unroll
            for (int mt = 0; mt < 4; mt++) {
                uint32_t off = (uint32_t)((buf * A_BUF +
                    (m_base + mt * 16 + lr) * A_STRIDE + kk + lc * 8) * 2);
                ldsm_x4(a[mt], uA + off);
            }
            #pragma unroll
            for (int ng = 0; ng < 2; ng++) {
                uint32_t off = (uint32_t)((buf * B_BUF +
                    (kk + lr) * B_STRIDE + n_base + ng * 16 + lc * 8) * 2);
                ldsm_x4t(b_hi[ng], uBh + off);
                ldsm_x4t(b_lo[ng], uBl + off);
            }
            #pragma unroll
            for (int mt = 0; mt < 4; mt++)
                #pragma unroll
                for (int ng = 0; ng < 2; ng++)
                    #pragma unroll
                    for (int h = 0; h < 2; h++) {
                        float* c = acc[mt][ng * 2 + h];
                        mma16816h(c, a[mt], &b_hi[ng][2 * h]);
                        mma16816h(c, a[mt], &b_lo[ng][2 * h]);
                    }
        }
    };

    const int niter = K / TBK;
    load_async(0, 0);
    cp_commit();
    for (int it = 0; it < niter; it++) {
        const int buf = it & 1;
        if (it + 1 < niter) {
            load_async(it + 1, buf ^ 1);
            cp_commit();
            cp_wait<1>();
        } else {
            cp_wait<0>();
        }
        __syncthreads();
        compute(buf);
        __syncthreads();
    }

    // epilogue
    #pragma unroll
    for (int mt = 0; mt < 4; mt++) {
        int r0 = m0 + m_base + mt * 16 + (lane >> 2);
        #pragma unroll
        for (int j = 0; j < 4; j++) {
            int col = n0 + n_base + j * 8 + (lane & 3) * 2;
            float bx = bias[col], by = bias[col + 1];
            float* c = acc[mt][j];
            float v00 = c[0] + bx, v01 = c[1] + by;
            float v10 = c[2] + bx, v11 = c[3] + by;
            if (RELU) {
                v00 = fmaxf(v00, 0.f); v01 = fmaxf(v01, 0.f);
                v10 = fmaxf(v10, 0.f); v11 = fmaxf(v11, 0.f);
            }
            if (WF32) {
                *(float2*)(Cf + (size_t)r0 * N + col)       = make_float2(v00, v01);
                *(float2*)(Cf + (size_t)(r0 + 8) * N + col) = make_float2(v10, v11);
            }
            if (WHALF) {
                __half2 p0; p0.x = __float2half_rn(v00); p0.y = __float2half_rn(v01);
                __half2 p1; p1.x = __float2half_rn(v10); p1.y = __float2half_rn(v11);
                *(__half2*)(Ch + (size_t)r0 * N + col)       = p0;
                *(__half2*)(Ch + (size_t)(r0 + 8) * N + col) = p1;
            }
        }
    }
}

// ---------------------------------------------------------------------------
// Transpose + fp16 convert: x (B, FDIM, SEQ) -> A (B*SEQ, FDIM)
// ---------------------------------------------------------------------------
__global__ __launch_bounds__(256)
void xT_cvt(const float* __restrict__ x, __half* __restrict__ o)
{
    __shared__ float t[32][33];
    int b = blockIdx.z;
    int f0 = blockIdx.x * 32, s0 = blockIdx.y * 32;
    const float* xb = x + (size_t)b * FDIM * SEQ;
    int tx = threadIdx.x, ty = threadIdx.y;
    #pragma unroll
    for (int i = ty; i < 32; i += 8) {
        int s = s0 + tx;
        t[i][tx] = (s < SEQ) ? xb[(size_t)(f0 + i) * SEQ + s] : 0.f;
    }
    __syncthreads();
    #pragma unroll
    for (int i = ty; i < 32; i += 8) {
        int s = s0 + i, f = f0 + tx;
        if (s < SEQ)
            o[((size_t)b * SEQ + s) * FDIM + f] = __float2half_rn(t[tx][i]);
    }
}

// ---------------------------------------------------------------------------
// fp32 -> fp16 hi/lo elementwise (weights), 4-wide
// ---------------------------------------------------------------------------
__global__ __launch_bounds__(256)
void cvt_hilo(const float* __restrict__ in, __half* __restrict__ hi,
              __half* __restrict__ lo, int n4)
{
    int i = blockIdx.x * 256 + threadIdx.x;
    if (i < n4) {
        float4 v = ((const float4*)in)[i];
        __half2 h0, h1, l0, l1;
        h0.x = __float2half_rn(v.x); h0.y = __float2half_rn(v.y);
        h1.x = __float2half_rn(v.z); h1.y = __float2half_rn(v.w);
        l0.x = __float2half_rn(v.x - __half2float(h0.x));
        l0.y = __float2half_rn(v.y - __half2float(h0.y));
        l1.x = __float2half_rn(v.z - __half2float(h1.x));
        l1.y = __float2half_rn(v.w - __half2float(h1.y));
        ((__half2*)hi)[i * 2]     = h0;
        ((__half2*)hi)[i * 2 + 1] = h1;
        ((__half2*)lo)[i * 2]     = l0;
        ((__half2*)lo)[i * 2 + 1] = l1;
    }
}

// ---------------------------------------------------------------------------
// Block reduction helper
// ---------------------------------------------------------------------------
__device__ __forceinline__ float block_sum(float v, float* sred) {
    int lane = threadIdx.x & 31, w = threadIdx.x >> 5;
    #pragma unroll
    for (int o = 16; o > 0; o >>= 1) v += __shfl_down_sync(0xffffffffu, v, o);
    if (lane == 0) sred[w] = v;
    __syncthreads();
    float s = (threadIdx.x < 8) ? sred[threadIdx.x] : 0.0f;
    if (w == 0) {
        #pragma unroll
        for (int o = 4; o > 0; o >>= 1) s += __shfl_down_sync(0xffffffffu, s, o);
        if (lane == 0) sred[0] = s;
    }
    __syncthreads();
    float r = sred[0];
    __syncthreads();
    return r;
}

// ---------------------------------------------------------------------------
// fp32 SGEMM (tiny q projection, M=100) — exact
// ---------------------------------------------------------------------------
#define BM 64
#define BN 64
#define BKt 16
__global__ __launch_bounds__(256)
void sgemm(const float* __restrict__ A, const float* __restrict__ Bm,
           const float* __restrict__ bias, float* __restrict__ C,
           int M, int N, int K)
{
    __shared__ float As[BKt][BM];
    __shared__ float Bs[BKt][BN];
    const int tid = threadIdx.x;
    const int n0 = blockIdx.x * BN;
    const int m0 = blockIdx.y * BM;
    const int tx = tid & 15, ty = tid >> 4;
    const int ar = tid >> 2, ac = (tid & 3) * 4;
    const int br = tid >> 4, bc = (tid & 15) * 4;
    float acc[4][4] = {};
    for (int k0 = 0; k0 < K; k0 += BKt) {
        float4 av;
        int arow = m0 + ar;
        if (arow < M) av = *(const float4*)(A + (size_t)arow * K + k0 + ac);
        else          av = make_float4(0.f, 0.f, 0.f, 0.f);
        As[ac + 0][ar] = av.x; As[ac + 1][ar] = av.y;
        As[ac + 2][ar] = av.z; As[ac + 3][ar] = av.w;
        *(float4*)&Bs[br][bc] = *(const float4*)(Bm + (size_t)(k0 + br) * N + n0 + bc);
        __syncthreads();
        #pragma unroll
        for (int kk = 0; kk < BKt; kk++) {
            float a[4], b[4];
            *(float4*)a = *(const float4*)&As[kk][ty * 4];
            *(float4*)b = *(const float4*)&Bs[kk][tx * 4];
            #pragma unroll
            for (int i = 0; i < 4; i++)
                #pragma unroll
                for (int j = 0; j < 4; j++)
                    acc[i][j] += a[i] * b[j];
        }
        __syncthreads();
    }
    #pragma unroll
    for (int i = 0; i < 4; i++) {
        int row = m0 + ty * 4 + i;
        if (row >= M) continue;
        #pragma unroll
        for (int j = 0; j < 4; j++) {
            int col = n0 + tx * 4 + j;
            C[(size_t)row * N + col] = acc[i][j] + bias[col];
        }
    }
}

// ---------------------------------------------------------------------------
// tgt_ln = layernorm(2 * query_embed) * g1 + be1
// ---------------------------------------------------------------------------
__global__ __launch_bounds__(256)
void ln_query(const float* __restrict__ qe, const float* __restrict__ g,
              const float* __restrict__ be, float* __restrict__ out)
{
    __shared__ float sred[8];
    int r = blockIdx.x, t = threadIdx.x;
    float v[3];
    float s = 0.0f;
    #pragma unroll
    for (int i = 0; i < 3; i++) { v[i] = 2.0f * qe[(size_t)r * D + t + i * 256]; s += v[i]; }
    float mean = block_sum(s, sred) * (1.0f / D);
    float vs = 0.0f;
    #pragma unroll
    for (int i = 0; i < 3; i++) { float d = v[i] - mean; vs += d * d; }
    float var = block_sum(vs, sred) * (1.0f / D);
    float inv = rsqrtf(var + EPS);
    #pragma unroll
    for (int i = 0; i < 3; i++) {
        int c = t + i * 256;
        out[(size_t)r * D + c] = (v[i] - mean) * inv * g[c] + be[c];
    }
}

// ---------------------------------------------------------------------------
// out = LN(res[rr] + inp[r]) ; optional fp16 copy
// ---------------------------------------------------------------------------
__global__ __launch_bounds__(256)
void ln_residual(const float* __restrict__ res, const float* __restrict__ inp,
                 const float* __restrict__ g, const float* __restrict__ be,
                 float* __restrict__ out, __half* __restrict__ oh, int bcast)
{
    __shared__ float sred[8];
    long r = blockIdx.x;
    long rr = bcast ? (r % KQ) : r;
    int t = threadIdx.x;
    float v[3];
    float s = 0.0f;
    #pragma unroll
    for (int i = 0; i < 3; i++) {
        int c = t + i * 256;
        v[i] = res[rr * D + c] + inp[r * D + c];
        s += v[i];
    }
    float mean = block_sum(s, sred) * (1.0f / D);
    float vs = 0.0f;
    #pragma unroll
    for (int i = 0; i < 3; i++) { float d = v[i] - mean; vs += d * d; }
    float var = block_sum(vs, sred) * (1.0f / D);
    float inv = rsqrtf(var + EPS);
    #pragma unroll
    for (int i = 0; i < 3; i++) {
        int c = t + i * 256;
        float o = (v[i] - mean) * inv * g[c] + be[c];
        out[r * D + c] = o;
        if (oh) oh[r * D + c] = __float2half_rn(o);
    }
}

// ---------------------------------------------------------------------------
// Fused cross attention. grid=(NHEAD, BATCH), 128 threads. Writes fp16 ctx.
// ---------------------------------------------------------------------------
#define QPAD 97
__global__ __launch_bounds__(128)
void attn_kernel(const float* __restrict__ Q, const float* __restrict__ Kb,
                 const float* __restrict__ Vb, __half* __restrict__ ch)
{
    extern __shared__ float sm[];
    float* Qs = sm;
    float* Ks = sm + KQ * QPAD;
    float* Vs = Ks + SEQ * HD;
    const int hh = blockIdx.x, b = blockIdx.y;
    const int t = threadIdx.x;

    for (int idx = t; idx < KQ * HD; idx += 128) {
        int k = idx / HD, d = idx - k * HD;
        Qs[k * QPAD + d] = Q[(size_t)k * D + hh * HD + d];
    }
    for (int idx = t; idx < SEQ * HD; idx += 128) {
        int s = idx / HD, d = idx - s * HD;
        size_t off = ((size_t)b * SEQ + s) * D + hh * HD + d;
        Ks[idx] = Kb[off];
        Vs[idx] = Vb[off];
    }
    __syncthreads();

    if (t < KQ) {
        const float scale = 0.102062072615966f;   // 1/sqrt(96)
        float sc[SEQ];
        float mx = -1e30f;
        #pragma unroll 7
        for (int s = 0; s < SEQ; s++) {
            float a = 0.0f;
            const float* qp = Qs + t * QPAD;
            const float* kp = Ks + s * HD;
            #pragma unroll 8
            for (int d = 0; d < HD; d++) a += qp[d] * kp[d];
            a *= scale;
            sc[s] = a;
            mx = fmaxf(mx, a);
        }
        float sum = 0.0f;
        #pragma unroll 7
        for (int s = 0; s < SEQ; s++) { sc[s] = expf(sc[s] - mx); sum += sc[s]; }
        float inv = 1.0f / sum;
        size_t ob = ((size_t)b * KQ + t) * D + hh * HD;
        #pragma unroll 8
        for (int d = 0; d < HD; d++) {
            float a = 0.0f;
            #pragma unroll 7
            for (int s = 0; s < SEQ; s++) a += sc[s] * Vs[s * HD + d];
            ch[ob + d] = __float2half_rn(a * inv);
        }
    }
}

// ---------------------------------------------------------------------------
// GroupFC
// ---------------------------------------------------------------------------
__global__ __launch_bounds__(256)
void groupfc(const float* __restrict__ H, const float* __restrict__ P,
             const float* __restrict__ db, float* __restrict__ out)
{
    const int k = blockIdx.x, b = blockIdx.y;
    const int t = threadIdx.x;
    float acc[GRP] = {};
    const float* hp = H + ((size_t)b * KQ + k) * D;
    const float* pp = P + (size_t)k * D * GRP;
    for (int d = t; d < D; d += 256) {
        float hv = hp[d];
        const float* q = pp + d * GRP;
        #pragma unroll
        for (int g = 0; g < GRP; g++) acc[g] += hv * q[g];
    }
    #pragma unroll
    for (int g = 0; g < GRP; g++)
        #pragma unroll
        for (int o = 16; o > 0; o >>= 1)
            acc[g] += __shfl_down_sync(0xffffffffu, acc[g], o);
    __shared__ float red[8][GRP];
    int w = t >> 5, lane = t & 31;
    if (lane == 0) {
        #pragma unroll
        for (int g = 0; g < GRP; g++) red[w][g] = acc[g];
    }
    __syncthreads();
    if (t < GRP) {
        float s = 0.0f;
        #pragma unroll
        for (int w2 = 0; w2 < 8; w2++) s += red[w2][t];
        out[(size_t)b * NC + k * GRP + t] = s + db[k * GRP + t];
    }
}

// ---------------------------------------------------------------------------
// Host launcher
// ---------------------------------------------------------------------------
extern "C" void kernel_launch(void* const* d_in, const int* in_sizes, int n_in,
                              void* d_out, int out_size)
{
    (void)in_sizes; (void)n_in; (void)out_size;
    const float* x        = (const float*)d_in[0];
    const float* W_embed  = (const float*)d_in[1];
    const float* b_embed  = (const float*)d_in[2];
    const float* query_embed = (const float*)d_in[3];
    const float* wq = (const float*)d_in[4];
    const float* wk = (const float*)d_in[5];
    const float* wv = (const float*)d_in[6];
    const float* bq = (const float*)d_in[7];
    const float* bk = (const float*)d_in[8];
    const float* bv = (const float*)d_in[9];
    const float* wo = (const float*)d_in[10];
    const float* bo = (const float*)d_in[11];
    const float* w1 = (const float*)d_in[12];
    const float* b1 = (const float*)d_in[13];
    const float* w2 = (const float*)d_in[14];
    const float* b2 = (const float*)d_in[15];
    const float* g1 = (const float*)d_in[16];
    const float* be1= (const float*)d_in[17];
    const float* g2 = (const float*)d_in[18];
    const float* be2= (const float*)d_in[19];
    const float* g3 = (const float*)d_in[20];
    const float* be3= (const float*)d_in[21];
    const float* dup_pool = (const float*)d_in[22];
    const float* dup_bias = (const float*)d_in[23];
    float* out = (float*)d_out;

    __half *xT, *memh, *ctxh, *t2h, *h1h;
    __half *Weh, *Wel, *wkh, *wkl, *wvh, *wvl, *woh, *wol, *w1h, *w1l, *w2h, *w2l;
    float *kb, *vb, *tln, *qb, *tmp, *tgt2, *h2, *hhp;
    cudaGetSymbolAddress((void**)&xT,   g_xT);
    cudaGetSymbolAddress((void**)&memh, g_memh);
    cudaGetSymbolAddress((void**)&ctxh, g_ctxh);
    cudaGetSymbolAddress((void**)&t2h,  g_t2h);
    cudaGetSymbolAddress((void**)&h1h,  g_h1h);
    cudaGetSymbolAddress((void**)&Weh,  g_We_hi);  cudaGetSymbolAddress((void**)&Wel,  g_We_lo);
    cudaGetSymbolAddress((void**)&wkh,  g_wk_hi);  cudaGetSymbolAddress((void**)&wkl,  g_wk_lo);
    cudaGetSymbolAddress((void**)&wvh,  g_wv_hi);  cudaGetSymbolAddress((void**)&wvl,  g_wv_lo);
    cudaGetSymbolAddress((void**)&woh,  g_wo_hi);  cudaGetSymbolAddress((void**)&wol,  g_wo_lo);
    cudaGetSymbolAddress((void**)&w1h,  g_w1_hi);  cudaGetSymbolAddress((void**)&w1l,  g_w1_lo);
    cudaGetSymbolAddress((void**)&w2h,  g_w2_hi);  cudaGetSymbolAddress((void**)&w2l,  g_w2_lo);
    cudaGetSymbolAddress((void**)&kb,   g_kbuf);
    cudaGetSymbolAddress((void**)&vb,   g_vbuf);
    cudaGetSymbolAddress((void**)&tln,  g_tgtln);
    cudaGetSymbolAddress((void**)&qb,   g_q);
    cudaGetSymbolAddress((void**)&tmp,  g_tmp);
    cudaGetSymbolAddress((void**)&tgt2, g_tgt2);
    cudaGetSymbolAddress((void**)&h2,   g_h2);
    cudaGetSymbolAddress((void**)&hhp,  g_h);

    const int BKQ = BATCH * KQ;     // 12800
    const int BS  = BATCH * SEQ;    // 6272

    static bool attr_set = false;
    if (!attr_set) {
        cudaFuncSetAttribute(mma_gemm<true,  false, true >, cudaFuncAttributeMaxDynamicSharedMemorySize, SMEM_GEMM);
        cudaFuncSetAttribute(mma_gemm<false, true,  false>, cudaFuncAttributeMaxDynamicSharedMemorySize, SMEM_GEMM);
        int smem_attn = (KQ * QPAD + 2 * SEQ * HD) * (int)sizeof(float);
        cudaFuncSetAttribute(attn_kernel, cudaFuncAttributeMaxDynamicSharedMemorySize, smem_attn);
        attr_set = true;
    }

    // 0) conversions
    xT_cvt<<<dim3(FDIM / 32, 2, BATCH), dim3(32, 8)>>>(x, xT);
    cvt_hilo<<<(FDIM * D / 4 + 255) / 256, 256>>>(W_embed, Weh, Wel, FDIM * D / 4);
    cvt_hilo<<<(D * D / 4 + 255) / 256, 256>>>(wk, wkh, wkl, D * D / 4);
    cvt_hilo<<<(D * D / 4 + 255) / 256, 256>>>(wv, wvh, wvl, D * D / 4);
    cvt_hilo<<<(D * D / 4 + 255) / 256, 256>>>(wo, woh, wol, D * D / 4);
    cvt_hilo<<<(D * FF / 4 + 255) / 256, 256>>>(w1, w1h, w1l, D * FF / 4);
    cvt_hilo<<<(FF * D / 4 + 255) / 256, 256>>>(w2, w2h, w2l, FF * D / 4);

    // 1) embed: mem = relu(xT @ W_embed + b_embed) -> fp16   (6272 x 768 x 2048)
    mma_gemm<true, false, true><<<dim3(D / TBN, BS / TBM), 256, SMEM_GEMM>>>(
        xT, Weh, Wel, b_embed, nullptr, memh, BS, D, FDIM);

    // 2) tgt_ln = LN(2 * query_embed)
    ln_query<<<KQ, 256>>>(query_embed, g1, be1, tln);

    // 3) q = tgt_ln @ wq + bq (tiny, fp32 exact)
    sgemm<<<dim3(D / BN, (KQ + BM - 1) / BM), 256>>>(tln, wq, bq, qb, KQ, D, D);

    // 4) k, v projections -> fp32
    mma_gemm<false, true, false><<<dim3(D / TBN, BS / TBM), 256, SMEM_GEMM>>>(
        memh, wkh, wkl, bk, kb, nullptr, BS, D, D);
    mma_gemm<false, true, false><<<dim3(D / TBN, BS / TBM), 256, SMEM_GEMM>>>(
        memh, wvh, wvl, bv, vb, nullptr, BS, D, D);

    // 5) attention -> ctx fp16
    {
        int smem = (KQ * QPAD + 2 * SEQ * HD) * (int)sizeof(float);
        attn_kernel<<<dim3(NHEAD, BATCH), 128, smem>>>(qb, kb, vb, ctxh);
    }

    // 6) attn_out = ctx @ wo + bo -> fp32
    mma_gemm<false, true, false><<<dim3(D / TBN, BKQ / TBM), 256, SMEM_GEMM>>>(
        ctxh, woh, wol, bo, tmp, nullptr, BKQ, D, D);

    // 7) tgt2 = LN(tgt_ln + attn_out) -> fp32 + fp16
    ln_residual<<<BKQ, 256>>>(tln, tmp, g2, be2, tgt2, t2h, 1);

    // 8) FFN
    mma_gemm<true, false, true><<<dim3(FF / TBN, BKQ / TBM), 256, SMEM_GEMM>>>(
        t2h, w1h, w1l, b1, nullptr, h1h, BKQ, FF, D);
    mma_gemm<false, true, false><<<dim3(D / TBN, BKQ / TBM), 256, SMEM_GEMM>>>(
        h1h, w2h, w2l, b2, h2, nullptr, BKQ, D, FF);

    // 9) h = LN(tgt2 + ffn)
    ln_residual<<<BKQ, 256>>>(tgt2, h2, g3, be3, hhp, nullptr, 0);

    // 10) group FC -> logits
    groupfc<<<dim3(KQ, BATCH), 256>>>(hhp, dup_pool, dup_bias, out);
}

// round 6
// speedup vs baseline: 3.7980x; 1.2559x over previous
#include <cuda_runtime.h>
#include <cuda_fp16.h>
#include <math.h>
#include <stdint.h>

// ---------------------------------------------------------------------------
// Problem constants
// ---------------------------------------------------------------------------
#define BATCH 128
#define SEQ   49
#define FDIM  2048
#define D     768
#define KQ    100
#define NHEAD 8
#define HD    96
#define FF    2048
#define NC    1000
#define GRP   10
#define EPS   1e-5f

// ---------------------------------------------------------------------------
// Scratch (static device globals; no allocation allowed)
// ---------------------------------------------------------------------------
// fp16 activation buffers (A operands, row-major [M, K])
__device__ __half g_xT  [BATCH * SEQ * FDIM];
__device__ __half g_memh[BATCH * SEQ * D];
__device__ __half g_ctxh[BATCH * KQ * D];
__device__ __half g_t2h [BATCH * KQ * D];
__device__ __half g_h1h [BATCH * KQ * FF];
// fp16 weight buffers (B operands, [K, N] row-major)
__device__ __half g_We[FDIM * D];
__device__ __half g_wk[D * D];
__device__ __half g_wv[D * D];
__device__ __half g_wo[D * D];
__device__ __half g_w1[D * FF];
__device__ __half g_w2[FF * D];
// fp32 buffers
__device__ float g_kbuf [BATCH * SEQ * D];
__device__ float g_vbuf [BATCH * SEQ * D];
__device__ float g_tgtln[KQ * D];
__device__ float g_q    [KQ * D];
__device__ float g_tmp  [BATCH * KQ * D];
__device__ float g_tgt2 [BATCH * KQ * D];
__device__ float g_h2   [BATCH * KQ * D];
__device__ float g_h    [BATCH * KQ * D];

// ---------------------------------------------------------------------------
// PTX helpers
// ---------------------------------------------------------------------------
__device__ __forceinline__ uint32_t smem_u32(const void* p) {
    return (uint32_t)__cvta_generic_to_shared(p);
}
__device__ __forceinline__ void ldsm_x4(uint32_t* d, uint32_t addr) {
    asm volatile("ldmatrix.sync.aligned.m8n8.x4.shared.b16 {%0,%1,%2,%3}, [%4];"
        : "=r"(d[0]), "=r"(d[1]), "=r"(d[2]), "=r"(d[3]) : "r"(addr));
}
__device__ __forceinline__ void ldsm_x4t(uint32_t* d, uint32_t addr) {
    asm volatile("ldmatrix.sync.aligned.m8n8.x4.trans.shared.b16 {%0,%1,%2,%3}, [%4];"
        : "=r"(d[0]), "=r"(d[1]), "=r"(d[2]), "=r"(d[3]) : "r"(addr));
}
__device__ __forceinline__ void mma16816h(float* c, const uint32_t* a, const uint32_t* b) {
    asm volatile("mma.sync.aligned.m16n8k16.row.col.f32.f16.f16.f32 "
        "{%0,%1,%2,%3}, {%4,%5,%6,%7}, {%8,%9}, {%0,%1,%2,%3};"
        : "+f"(c[0]), "+f"(c[1]), "+f"(c[2]), "+f"(c[3])
        : "r"(a[0]), "r"(a[1]), "r"(a[2]), "r"(a[3]), "r"(b[0]), "r"(b[1]));
}
__device__ __forceinline__ void cp_async16(uint32_t dst, const void* src) {
    asm volatile("cp.async.cg.shared.global [%0], [%1], 16;"
        :: "r"(dst), "l"(src) : "memory");
}
__device__ __forceinline__ void cp_commit() {
    asm volatile("cp.async.commit_group;" ::: "memory");
}
template<int N_>
__device__ __forceinline__ void cp_wait() {
    asm volatile("cp.async.wait_group %0;" :: "n"(N_) : "memory");
}

// ---------------------------------------------------------------------------
// Tensor-core GEMM: C[M,N] = A_fp16[M,K] @ B_fp16[K,N] + bias
// CTA tile 128x128, BK=32, 256 threads (8 warps: 2 in M x 4 in N),
// warp tile 64x32 -> 16 MMAs per 6 ldmatrix per k16.
// 3-stage cp.async circular pipeline, ONE __syncthreads per k-iter.
// Requires: M % 128 == 0, N % 128 == 0, K % 32 == 0.
// ---------------------------------------------------------------------------
#define TBM 128
#define TBN 128
#define TBK 32
#define NSTG 3
#define A_STRIDE (TBK + 8)      // 40 halfs
#define B_STRIDE (TBN + 8)      // 136 halfs
#define A_BUF (TBM * A_STRIDE)  // 5120 halfs
#define B_BUF (TBK * B_STRIDE)  // 4352 halfs
#define STAGE_HALFS (A_BUF + B_BUF)              // 9472
#define SMEM_GEMM (NSTG * STAGE_HALFS * 2)       // 56832 B

template<bool RELU, bool WF32, bool WHALF>
__global__ __launch_bounds__(256)
void mma_gemm(const __half* __restrict__ A, const __half* __restrict__ B,
              const float* __restrict__ bias,
              float* __restrict__ Cf, __half* __restrict__ Ch,
              int M, int N, int K)
{
    extern __shared__ __align__(16) unsigned char smem_raw[];
    __half* sA = (__half*)smem_raw;               // [NSTG][A_BUF]
    __half* sB = sA + NSTG * A_BUF;               // [NSTG][B_BUF]

    const int tid  = threadIdx.x;
    const int n0   = blockIdx.x * TBN;
    const int m0   = blockIdx.y * TBM;
    const int lane = tid & 31;
    const int warp = tid >> 5;
    const int m_base = (warp & 1) * 64;           // 2 warps in M
    const int n_base = (warp >> 1) * 32;          // 4 warps in N

    const int ar = tid >> 2,  ac = (tid & 3) * 8;    // A: 128r x 32c (2 rows/thr)
    const int br = tid >> 4,  bc = (tid & 15) * 8;   // B: 32r x 128c (2 rows/thr)

    const uint32_t uA = smem_u32(sA);
    const uint32_t uB = smem_u32(sB);

    float acc[4][4][4];
    #pragma unroll
    for (int i = 0; i < 4; i++)
        #pragma unroll
        for (int j = 0; j < 4; j++)
            #pragma unroll
            for (int k = 0; k < 4; k++) acc[i][j][k] = 0.0f;

    auto load_async = [&](int it, int buf) {
        const int k0 = it * TBK;
        uint32_t dA = uA + (uint32_t)((buf * A_BUF + ar * A_STRIDE + ac) * 2);
        const __half* gA = A + (size_t)(m0 + ar) * K + k0 + ac;
        cp_async16(dA, gA);
        cp_async16(dA + (uint32_t)(64 * A_STRIDE * 2), gA + (size_t)64 * K);
        uint32_t dB = uB + (uint32_t)((buf * B_BUF + br * B_STRIDE + bc) * 2);
        const __half* gB = B + (size_t)(br) * N + (size_t)k0 * N + n0 + bc;
        cp_async16(dB, gB);
        cp_async16(dB + (uint32_t)(16 * B_STRIDE * 2), gB + (size_t)16 * N);
    };

    const int lr = lane & 15;
    const int lc = lane >> 4;

    auto compute = [&](int buf) {
        #pragma unroll
        for (int kk = 0; kk < TBK; kk += 16) {
            uint32_t a[4][4], b[2][4];
            #pragma unroll
            for (int mt = 0; mt < 4; mt++) {
                uint32_t off = (uint32_t)((buf * A_BUF +
                    (m_base + mt * 16 + lr) * A_STRIDE + kk + lc * 8) * 2);
                ldsm_x4(a[mt], uA + off);
            }
            #pragma unroll
            for (int ng = 0; ng < 2; ng++) {
                uint32_t off = (uint32_t)((buf * B_BUF +
                    (kk + lr) * B_STRIDE + n_base + ng * 16 + lc * 8) * 2);
                ldsm_x4t(b[ng], uB + off);
            }
            #pragma unroll
            for (int mt = 0; mt < 4; mt++)
                #pragma unroll
                for (int ng = 0; ng < 2; ng++)
                    #pragma unroll
                    for (int h = 0; h < 2; h++)
                        mma16816h(acc[mt][ng * 2 + h], a[mt], &b[ng][2 * h]);
        }
    };

    const int niter = K / TBK;
    #pragma unroll
    for (int s = 0; s < NSTG - 1; s++) {
        if (s < niter) load_async(s, s);
        cp_commit();
    }
    int buf = 0;
    for (int it = 0; it < niter; it++) {
        cp_wait<NSTG - 2>();
        __syncthreads();
        compute(buf);
        const int nx = it + NSTG - 1;
        if (nx < niter) {
            int nbuf = buf + NSTG - 1; if (nbuf >= NSTG) nbuf -= NSTG;
            load_async(nx, nbuf);
        }
        cp_commit();
        if (++buf == NSTG) buf = 0;
    }

    // epilogue
    #pragma unroll
    for (int mt = 0; mt < 4; mt++) {
        int r0 = m0 + m_base + mt * 16 + (lane >> 2);
        #pragma unroll
        for (int j = 0; j < 4; j++) {
            int col = n0 + n_base + j * 8 + (lane & 3) * 2;
            float bx = bias[col], by = bias[col + 1];
            float* c = acc[mt][j];
            float v00 = c[0] + bx, v01 = c[1] + by;
            float v10 = c[2] + bx, v11 = c[3] + by;
            if (RELU) {
                v00 = fmaxf(v00, 0.f); v01 = fmaxf(v01, 0.f);
                v10 = fmaxf(v10, 0.f); v11 = fmaxf(v11, 0.f);
            }
            if (WF32) {
                *(float2*)(Cf + (size_t)r0 * N + col)       = make_float2(v00, v01);
                *(float2*)(Cf + (size_t)(r0 + 8) * N + col) = make_float2(v10, v11);
            }
            if (WHALF) {
                __half2 p0; p0.x = __float2half_rn(v00); p0.y = __float2half_rn(v01);
                __half2 p1; p1.x = __float2half_rn(v10); p1.y = __float2half_rn(v11);
                *(__half2*)(Ch + (size_t)r0 * N + col)       = p0;
                *(__half2*)(Ch + (size_t)(r0 + 8) * N + col) = p1;
            }
        }
    }
}

// ---------------------------------------------------------------------------
// Transpose + fp16 convert: x (B, FDIM, SEQ) -> A (B*SEQ, FDIM)
// ---------------------------------------------------------------------------
__global__ __launch_bounds__(256)
void xT_cvt(const float* __restrict__ x, __half* __restrict__ o)
{
    __shared__ float t[32][33];
    int b = blockIdx.z;
    int f0 = blockIdx.x * 32, s0 = blockIdx.y * 32;
    const float* xb = x + (size_t)b * FDIM * SEQ;
    int tx = threadIdx.x, ty = threadIdx.y;
    #pragma unroll
    for (int i = ty; i < 32; i += 8) {
        int s = s0 + tx;
        t[i][tx] = (s < SEQ) ? xb[(size_t)(f0 + i) * SEQ + s] : 0.f;
    }
    __syncthreads();
    #pragma unroll
    for (int i = ty; i < 32; i += 8) {
        int s = s0 + i, f = f0 + tx;
        if (s < SEQ)
            o[((size_t)b * SEQ + s) * FDIM + f] = __float2half_rn(t[tx][i]);
    }
}

// ---------------------------------------------------------------------------
// fp32 -> fp16 elementwise (weights), 4-wide
// ---------------------------------------------------------------------------
__global__ __launch_bounds__(256)
void cvt_f16(const float* __restrict__ in, __half* __restrict__ o, int n4)
{
    int i = blockIdx.x * 256 + threadIdx.x;
    if (i < n4) {
        float4 v = ((const float4*)in)[i];
        __half2 h0, h1;
        h0.x = __float2half_rn(v.x); h0.y = __float2half_rn(v.y);
        h1.x = __float2half_rn(v.z); h1.y = __float2half_rn(v.w);
        ((__half2*)o)[i * 2]     = h0;
        ((__half2*)o)[i * 2 + 1] = h1;
    }
}

// ---------------------------------------------------------------------------
// Block reduction helper
// ---------------------------------------------------------------------------
__device__ __forceinline__ float block_sum(float v, float* sred) {
    int lane = threadIdx.x & 31, w = threadIdx.x >> 5;
    #pragma unroll
    for (int o = 16; o > 0; o >>= 1) v += __shfl_down_sync(0xffffffffu, v, o);
    if (lane == 0) sred[w] = v;
    __syncthreads();
    float s = (threadIdx.x < 8) ? sred[threadIdx.x] : 0.0f;
    if (w == 0) {
        #pragma unroll
        for (int o = 4; o > 0; o >>= 1) s += __shfl_down_sync(0xffffffffu, s, o);
        if (lane == 0) sred[0] = s;
    }
    __syncthreads();
    float r = sred[0];
    __syncthreads();
    return r;
}

// ---------------------------------------------------------------------------
// fp32 SGEMM (tiny q projection, M=100) — exact
// ---------------------------------------------------------------------------
#define BM 64
#define BN 64
#define BKt 16
__global__ __launch_bounds__(256)
void sgemm(const float* __restrict__ A, const float* __restrict__ Bm,
           const float* __restrict__ bias, float* __restrict__ C,
           int M, int N, int K)
{
    __shared__ float As[BKt][BM];
    __shared__ float Bs[BKt][BN];
    const int tid = threadIdx.x;
    const int n0 = blockIdx.x * BN;
    const int m0 = blockIdx.y * BM;
    const int tx = tid & 15, ty = tid >> 4;
    const int ar = tid >> 2, ac = (tid & 3) * 4;
    const int br = tid >> 4, bc = (tid & 15) * 4;
    float acc[4][4] = {};
    for (int k0 = 0; k0 < K; k0 += BKt) {
        float4 av;
        int arow = m0 + ar;
        if (arow < M) av = *(const float4*)(A + (size_t)arow * K + k0 + ac);
        else          av = make_float4(0.f, 0.f, 0.f, 0.f);
        As[ac + 0][ar] = av.x; As[ac + 1][ar] = av.y;
        As[ac + 2][ar] = av.z; As[ac + 3][ar] = av.w;
        *(float4*)&Bs[br][bc] = *(const float4*)(Bm + (size_t)(k0 + br) * N + n0 + bc);
        __syncthreads();
        #pragma unroll
        for (int kk = 0; kk < BKt; kk++) {
            float a[4], b[4];
            *(float4*)a = *(const float4*)&As[kk][ty * 4];
            *(float4*)b = *(const float4*)&Bs[kk][tx * 4];
            #pragma unroll
            for (int i = 0; i < 4; i++)
                #pragma unroll
                for (int j = 0; j < 4; j++)
                    acc[i][j] += a[i] * b[j];
        }
        __syncthreads();
    }
    #pragma unroll
    for (int i = 0; i < 4; i++) {
        int row = m0 + ty * 4 + i;
        if (row >= M) continue;
        #pragma unroll
        for (int j = 0; j < 4; j++) {
            int col = n0 + tx * 4 + j;
            C[(size_t)row * N + col] = acc[i][j] + bias[col];
        }
    }
}

// ---------------------------------------------------------------------------
// tgt_ln = layernorm(2 * query_embed) * g1 + be1
// ---------------------------------------------------------------------------
__global__ __launch_bounds__(256)
void ln_query(const float* __restrict__ qe, const float* __restrict__ g,
              const float* __restrict__ be, float* __restrict__ out)
{
    __shared__ float sred[8];
    int r = blockIdx.x, t = threadIdx.x;
    float v[3];
    float s = 0.0f;
    #pragma unroll
    for (int i = 0; i < 3; i++) { v[i] = 2.0f * qe[(size_t)r * D + t + i * 256]; s += v[i]; }
    float mean = block_sum(s, sred) * (1.0f / D);
    float vs = 0.0f;
    #pragma unroll
    for (int i = 0; i < 3; i++) { float d = v[i] - mean; vs += d * d; }
    float var = block_sum(vs, sred) * (1.0f / D);
    float inv = rsqrtf(var + EPS);
    #pragma unroll
    for (int i = 0; i < 3; i++) {
        int c = t + i * 256;
        out[(size_t)r * D + c] = (v[i] - mean) * inv * g[c] + be[c];
    }
}

// ---------------------------------------------------------------------------
// out = LN(res[rr] + inp[r]) ; optional fp16 copy
// ---------------------------------------------------------------------------
__global__ __launch_bounds__(256)
void ln_residual(const float* __restrict__ res, const float* __restrict__ inp,
                 const float* __restrict__ g, const float* __restrict__ be,
                 float* __restrict__ out, __half* __restrict__ oh, int bcast)
{
    __shared__ float sred[8];
    long r = blockIdx.x;
    long rr = bcast ? (r % KQ) : r;
    int t = threadIdx.x;
    float v[3];
    float s = 0.0f;
    #pragma unroll
    for (int i = 0; i < 3; i++) {
        int c = t + i * 256;
        v[i] = res[rr * D + c] + inp[r * D + c];
        s += v[i];
    }
    float mean = block_sum(s, sred) * (1.0f / D);
    float vs = 0.0f;
    #pragma unroll
    for (int i = 0; i < 3; i++) { float d = v[i] - mean; vs += d * d; }
    float var = block_sum(vs, sred) * (1.0f / D);
    float inv = rsqrtf(var + EPS);
    #pragma unroll
    for (int i = 0; i < 3; i++) {
        int c = t + i * 256;
        float o = (v[i] - mean) * inv * g[c] + be[c];
        out[r * D + c] = o;
        if (oh) oh[r * D + c] = __float2half_rn(o);
    }
}

// ---------------------------------------------------------------------------
// Fused cross attention. grid=(NHEAD, BATCH), 128 threads. Writes fp16 ctx.
// ---------------------------------------------------------------------------
#define QPAD 97
__global__ __launch_bounds__(128)
void attn_kernel(const float* __restrict__ Q, const float* __restrict__ Kb,
                 const float* __restrict__ Vb, __half* __restrict__ ch)
{
    extern __shared__ float sm[];
    float* Qs = sm;
    float* Ks = sm + KQ * QPAD;
    float* Vs = Ks + SEQ * HD;
    const int hh = blockIdx.x, b = blockIdx.y;
    const int t = threadIdx.x;

    for (int idx = t; idx < KQ * HD; idx += 128) {
        int k = idx / HD, d = idx - k * HD;
        Qs[k * QPAD + d] = Q[(size_t)k * D + hh * HD + d];
    }
    for (int idx = t; idx < SEQ * HD; idx += 128) {
        int s = idx / HD, d = idx - s * HD;
        size_t off = ((size_t)b * SEQ + s) * D + hh * HD + d;
        Ks[idx] = Kb[off];
        Vs[idx] = Vb[off];
    }
    __syncthreads();

    if (t < KQ) {
        const float scale = 0.102062072615966f;   // 1/sqrt(96)
        float sc[SEQ];
        float mx = -1e30f;
        #pragma unroll 7
        for (int s = 0; s < SEQ; s++) {
            float a = 0.0f;
            const float* qp = Qs + t * QPAD;
            const float* kp = Ks + s * HD;
            #pragma unroll 8
            for (int d = 0; d < HD; d++) a += qp[d] * kp[d];
            a *= scale;
            sc[s] = a;
            mx = fmaxf(mx, a);
        }
        float sum = 0.0f;
        #pragma unroll 7
        for (int s = 0; s < SEQ; s++) { sc[s] = expf(sc[s] - mx); sum += sc[s]; }
        float inv = 1.0f / sum;
        size_t ob = ((size_t)b * KQ + t) * D + hh * HD;
        #pragma unroll 8
        for (int d = 0; d < HD; d++) {
            float a = 0.0f;
            #pragma unroll 7
            for (int s = 0; s < SEQ; s++) a += sc[s] * Vs[s * HD + d];
            ch[ob + d] = __float2half_rn(a * inv);
        }
    }
}

// ---------------------------------------------------------------------------
// GroupFC
// ---------------------------------------------------------------------------
__global__ __launch_bounds__(256)
void groupfc(const float* __restrict__ H, const float* __restrict__ P,
             const float* __restrict__ db, float* __restrict__ out)
{
    const int k = blockIdx.x, b = blockIdx.y;
    const int t = threadIdx.x;
    float acc[GRP] = {};
    const float* hp = H + ((size_t)b * KQ + k) * D;
    const float* pp = P + (size_t)k * D * GRP;
    for (int d = t; d < D; d += 256) {
        float hv = hp[d];
        const float* q = pp + d * GRP;
        #pragma unroll
        for (int g = 0; g < GRP; g++) acc[g] += hv * q[g];
    }
    #pragma unroll
    for (int g = 0; g < GRP; g++)
        #pragma unroll
        for (int o = 16; o > 0; o >>= 1)
            acc[g] += __shfl_down_sync(0xffffffffu, acc[g], o);
    __shared__ float red[8][GRP];
    int w = t >> 5, lane = t & 31;
    if (lane == 0) {
        #pragma unroll
        for (int g = 0; g < GRP; g++) red[w][g] = acc[g];
    }
    __syncthreads();
    if (t < GRP) {
        float s = 0.0f;
        #pragma unroll
        for (int w2 = 0; w2 < 8; w2++) s += red[w2][t];
        out[(size_t)b * NC + k * GRP + t] = s + db[k * GRP + t];
    }
}

// ---------------------------------------------------------------------------
// Host launcher
// ---------------------------------------------------------------------------
extern "C" void kernel_launch(void* const* d_in, const int* in_sizes, int n_in,
                              void* d_out, int out_size)
{
    (void)in_sizes; (void)n_in; (void)out_size;
    const float* x        = (const float*)d_in[0];
    const float* W_embed  = (const float*)d_in[1];
    const float* b_embed  = (const float*)d_in[2];
    const float* query_embed = (const float*)d_in[3];
    const float* wq = (const float*)d_in[4];
    const float* wk = (const float*)d_in[5];
    const float* wv = (const float*)d_in[6];
    const float* bq = (const float*)d_in[7];
    const float* bk = (const float*)d_in[8];
    const float* bv = (const float*)d_in[9];
    const float* wo = (const float*)d_in[10];
    const float* bo = (const float*)d_in[11];
    const float* w1 = (const float*)d_in[12];
    const float* b1 = (const float*)d_in[13];
    const float* w2 = (const float*)d_in[14];
    const float* b2 = (const float*)d_in[15];
    const float* g1 = (const float*)d_in[16];
    const float* be1= (const float*)d_in[17];
    const float* g2 = (const float*)d_in[18];
    const float* be2= (const float*)d_in[19];
    const float* g3 = (const float*)d_in[20];
    const float* be3= (const float*)d_in[21];
    const float* dup_pool = (const float*)d_in[22];
    const float* dup_bias = (const float*)d_in[23];
    float* out = (float*)d_out;

    __half *xT, *memh, *ctxh, *t2h, *h1h;
    __half *We, *wkc, *wvc, *woc, *w1c, *w2c;
    float *kb, *vb, *tln, *qb, *tmp, *tgt2, *h2, *hhp;
    cudaGetSymbolAddress((void**)&xT,   g_xT);
    cudaGetSymbolAddress((void**)&memh, g_memh);
    cudaGetSymbolAddress((void**)&ctxh, g_ctxh);
    cudaGetSymbolAddress((void**)&t2h,  g_t2h);
    cudaGetSymbolAddress((void**)&h1h,  g_h1h);
    cudaGetSymbolAddress((void**)&We,   g_We);
    cudaGetSymbolAddress((void**)&wkc,  g_wk);
    cudaGetSymbolAddress((void**)&wvc,  g_wv);
    cudaGetSymbolAddress((void**)&woc,  g_wo);
    cudaGetSymbolAddress((void**)&w1c,  g_w1);
    cudaGetSymbolAddress((void**)&w2c,  g_w2);
    cudaGetSymbolAddress((void**)&kb,   g_kbuf);
    cudaGetSymbolAddress((void**)&vb,   g_vbuf);
    cudaGetSymbolAddress((void**)&tln,  g_tgtln);
    cudaGetSymbolAddress((void**)&qb,   g_q);
    cudaGetSymbolAddress((void**)&tmp,  g_tmp);
    cudaGetSymbolAddress((void**)&tgt2, g_tgt2);
    cudaGetSymbolAddress((void**)&h2,   g_h2);
    cudaGetSymbolAddress((void**)&hhp,  g_h);

    const int BKQ = BATCH * KQ;     // 12800
    const int BS  = BATCH * SEQ;    // 6272

    static bool attr_set = false;
    if (!attr_set) {
        cudaFuncSetAttribute(mma_gemm<true,  false, true >, cudaFuncAttributeMaxDynamicSharedMemorySize, SMEM_GEMM);
        cudaFuncSetAttribute(mma_gemm<false, true,  false>, cudaFuncAttributeMaxDynamicSharedMemorySize, SMEM_GEMM);
        int smem_attn = (KQ * QPAD + 2 * SEQ * HD) * (int)sizeof(float);
        cudaFuncSetAttribute(attn_kernel, cudaFuncAttributeMaxDynamicSharedMemorySize, smem_attn);
        attr_set = true;
    }

    // 0) conversions
    xT_cvt<<<dim3(FDIM / 32, 2, BATCH), dim3(32, 8)>>>(x, xT);
    cvt_f16<<<(FDIM * D / 4 + 255) / 256, 256>>>(W_embed, We, FDIM * D / 4);
    cvt_f16<<<(D * D / 4 + 255) / 256, 256>>>(wk, wkc, D * D / 4);
    cvt_f16<<<(D * D / 4 + 255) / 256, 256>>>(wv, wvc, D * D / 4);
    cvt_f16<<<(D * D / 4 + 255) / 256, 256>>>(wo, woc, D * D / 4);
    cvt_f16<<<(D * FF / 4 + 255) / 256, 256>>>(w1, w1c, D * FF / 4);
    cvt_f16<<<(FF * D / 4 + 255) / 256, 256>>>(w2, w2c, FF * D / 4);

    // 1) embed: mem = relu(xT @ W_embed + b_embed) -> fp16   (6272 x 768 x 2048)
    mma_gemm<true, false, true><<<dim3(D / TBN, BS / TBM), 256, SMEM_GEMM>>>(
        xT, We, b_embed, nullptr, memh, BS, D, FDIM);

    // 2) tgt_ln = LN(2 * query_embed)
    ln_query<<<KQ, 256>>>(query_embed, g1, be1, tln);

    // 3) q = tgt_ln @ wq + bq (tiny, fp32 exact)
    sgemm<<<dim3(D / BN, (KQ + BM - 1) / BM), 256>>>(tln, wq, bq, qb, KQ, D, D);

    // 4) k, v projections -> fp32
    mma_gemm<false, true, false><<<dim3(D / TBN, BS / TBM), 256, SMEM_GEMM>>>(
        memh, wkc, bk, kb, nullptr, BS, D, D);
    mma_gemm<false, true, false><<<dim3(D / TBN, BS / TBM), 256, SMEM_GEMM>>>(
        memh, wvc, bv, vb, nullptr, BS, D, D);

    // 5) attention -> ctx fp16
    {
        int smem = (KQ * QPAD + 2 * SEQ * HD) * (int)sizeof(float);
        attn_kernel<<<dim3(NHEAD, BATCH), 128, smem>>>(qb, kb, vb, ctxh);
    }

    // 6) attn_out = ctx @ wo + bo -> fp32
    mma_gemm<false, true, false><<<dim3(D / TBN, BKQ / TBM), 256, SMEM_GEMM>>>(
        ctxh, woc, bo, tmp, nullptr, BKQ, D, D);

    // 7) tgt2 = LN(tgt_ln + attn_out) -> fp32 + fp16
    ln_residual<<<BKQ, 256>>>(tln, tmp, g2, be2, tgt2, t2h, 1);

    // 8) FFN
    mma_gemm<true, false, true><<<dim3(FF / TBN, BKQ / TBM), 256, SMEM_GEMM>>>(
        t2h, w1c, b1, nullptr, h1h, BKQ, FF, D);
    mma_gemm<false, true, false><<<dim3(D / TBN, BKQ / TBM), 256, SMEM_GEMM>>>(
        h1h, w2c, b2, h2, nullptr, BKQ, D, FF);

    // 9) h = LN(tgt2 + ffn)
    ln_residual<<<BKQ, 256>>>(tgt2, h2, g3, be3, hhp, nullptr, 0);

    // 10) group FC -> logits
    groupfc<<<dim3(KQ, BATCH), 256>>>(hhp, dup_pool, dup_bias, out);
}